// round 12
// baseline (speedup 1.0000x reference)
#include <cuda_runtime.h>
#include <cuda_fp16.h>
#include <cstdint>

// ---------------- problem constants ----------------
#define BB  4
#define SS  2048
#define DD  512
#define HH  8
#define DHH 64
#define FF  2048
#define NLL 4
#define MM  (BB*SS)      // 8192 rows
#define CC  64           // attention chunk length
#define NCC (SS/CC)      // 32 chunks
#define BHH (BB*HH)      // 32 (b,h) pairs

__device__ __forceinline__ uint32_t smem_u32(const void* p) {
    uint32_t a;
    asm("{ .reg .u64 t; cvta.to.shared.u64 t, %1; cvt.u32.u64 %0, t; }" : "=r"(a) : "l"(p));
    return a;
}

// ---------------- scratch (device globals; no allocs allowed) ----------------
__device__ float g_h[MM*DD];
__device__ float g_q[MM*DD];          // holds phi(q) after QKV
__device__ float g_k[MM*DD];          // holds masked phi(k) after QKV
__device__ float g_v[MM*DD];
__device__ float g_S[(size_t)BHH*NCC*DHH*DHH];
__device__ float g_ks[BHH*NCC*DHH];
__device__ int   g_len[BB];

// fp16 activations (single-rounded)
__device__ __align__(16) __half g_hf[MM*DD];             // residual stream as GEMM-A
__device__ __align__(16) __half g_af[MM*DD];             // attention output
__device__ __align__(16) __half g_tf[(size_t)MM*FF];     // FFN hidden

// transposed weights as fp16 hi/lo pairs: layout [N][K]
__device__ __align__(16) __half g_wq_h[NLL*DD*DD], g_wq_l[NLL*DD*DD];
__device__ __align__(16) __half g_wk_h[NLL*DD*DD], g_wk_l[NLL*DD*DD];
__device__ __align__(16) __half g_wv_h[NLL*DD*DD], g_wv_l[NLL*DD*DD];
__device__ __align__(16) __half g_wo_h[NLL*DD*DD], g_wo_l[NLL*DD*DD];
__device__ __align__(16) __half g_w1_h[NLL*FF*DD], g_w1_l[NLL*FF*DD];
__device__ __align__(16) __half g_w2_h[NLL*DD*FF], g_w2_l[NLL*DD*FF];

__device__ __forceinline__ float phi_f(float u) { return u > 0.f ? u + 1.f : __expf(u); }

__device__ __forceinline__ void split_h(float x, __half& h, __half& l) {
    h = __float2half_rn(x);
    l = __float2half_rn(x - __half2float(h));
}

// ---------------- lengths ----------------
__global__ void len_kernel(const int* __restrict__ x) {
    __shared__ int red[256];
    int b = blockIdx.x, tid = threadIdx.x;
    int cnt = 0;
    for (int s = tid; s < SS; s += 256) cnt += (x[b*SS + s] != 0);
    red[tid] = cnt; __syncthreads();
    for (int off = 128; off; off >>= 1) {
        if (tid < off) red[tid] += red[tid + off];
        __syncthreads();
    }
    if (tid == 0) g_len[b] = red[0];
}

// ---------------- embedding + positional (+ fp16 round) ----------------
__global__ void embed_kernel(const int* __restrict__ x,
                             const float* __restrict__ emb,
                             const float* __restrict__ pe) {
    int idx = blockIdx.x * 256 + threadIdx.x;
    if (idx >= MM * (DD/4)) return;
    int i  = idx >> 7;
    int d4 = idx & 127;
    int s  = i & (SS - 1);
    int tok = x[i];
    float4 e = ((const float4*)emb)[(size_t)tok * (DD/4) + d4];
    float4 p = ((const float4*)pe)[(size_t)s * (DD/4) + d4];
    float4 o;
    o.x = e.x + p.x; o.y = e.y + p.y; o.z = e.z + p.z; o.w = e.w + p.w;
    ((float4*)g_h)[idx] = o;
    size_t e0 = (size_t)idx * 4;
    g_hf[e0+0] = __float2half_rn(o.x);
    g_hf[e0+1] = __float2half_rn(o.y);
    g_hf[e0+2] = __float2half_rn(o.z);
    g_hf[e0+3] = __float2half_rn(o.w);
}

// ---------------- batched weight transpose + split (24 matrices, one launch) ----
struct WtcArgs {
    const float* src[24];
    __half* oh[24];
    __half* ol[24];
    int K[24], N[24];
};
__global__ void wtc_all_kernel(WtcArgs p) {
    __shared__ float t[32][33];
    int m = blockIdx.z;
    int K = p.K[m], N = p.N[m];
    int n0 = blockIdx.x * 32, k0 = blockIdx.y * 32;
    if (n0 >= N || k0 >= K) return;
    const float* W = p.src[m];
    __half *oh = p.oh[m], *ol = p.ol[m];
    int tx = threadIdx.x, ty = threadIdx.y;   // 32x8
    #pragma unroll
    for (int i = 0; i < 32; i += 8)
        t[ty + i][tx] = W[(size_t)(k0 + ty + i) * N + n0 + tx];
    __syncthreads();
    #pragma unroll
    for (int i = 0; i < 32; i += 8) {
        float v = t[tx][ty + i];
        size_t o = (size_t)(n0 + ty + i) * K + k0 + tx;
        split_h(v, oh[o], ol[o]);
    }
}

// ---------------- 2-term fp16 GEMM via warp mma.sync ----------------
// C[M,N] = A[M,K] * B[N,K]^T + bias ; A single fp16, B as fp16 (hi,lo) pair.
// C = Af*Bh + Af*Bl.  Block 128x128, BK=64, 256 thr, warp tile 64x32.
// 2-stage cp.async pipeline (BK=64 halves loop count), 8-chunk XOR swizzle on
// 128B-pitch rows, 2 CTAs/SM.  pmode (float-out path): 0=none, 1=phi, 2=masked phi.
struct GTArgs {
    const __half *Af;
    const __half *Bh[3], *Bl[3];
    const float* bias[3];
    float* outf[3];
    __half* outh[3];
    int pmode[3];
    int N, K;
};

#define STAGES 2
#define TILE_BYTES 16384                   // 128 rows x 128B (swizzled)
#define STAGE_BYTES (3*TILE_BYTES)         // Af,Bh,Bl = 49152
#define GM_SMEM_BYTES (STAGES*STAGE_BYTES) // 98304

// swizzled in-tile byte offset for (row, 16B-chunk c in 0..7): row*128 + ((c ^ (row&7))<<4)
__device__ __forceinline__ uint32_t swz8(int row, int c) {
    return (uint32_t)(row * 128 + ((c ^ (row & 7)) << 4));
}

#define MMA_F16(d, a, b) \
    asm volatile("mma.sync.aligned.m16n8k16.row.col.f32.f16.f16.f32 " \
        "{%0,%1,%2,%3}, {%4,%5,%6,%7}, {%8,%9}, {%0,%1,%2,%3};" \
        : "+f"((d)[0]), "+f"((d)[1]), "+f"((d)[2]), "+f"((d)[3]) \
        : "r"((a)[0]), "r"((a)[1]), "r"((a)[2]), "r"((a)[3]), "r"((b)[0]), "r"((b)[1]))

#define LDMX4(r, addr) \
    asm volatile("ldmatrix.sync.aligned.m8n8.x4.shared.b16 {%0,%1,%2,%3}, [%4];" \
        : "=r"((r)[0]), "=r"((r)[1]), "=r"((r)[2]), "=r"((r)[3]) : "r"(addr))

template<int RELU, int OUTH>
__global__ void __launch_bounds__(256, 2) gemm_mma(GTArgs p) {
    extern __shared__ __half sm[];
    const uint32_t sbase = smem_u32(sm);
    const int z = blockIdx.z;
    const int N = p.N, K = p.K;
    const int tid = threadIdx.x;
    const int m0 = blockIdx.y * 128, n0 = blockIdx.x * 128;

    // ---- loader: thread owns row rA (0..127), 4 chunks starting at c0; 12x16B/stage
    const int rA = tid >> 1;           // 0..127
    const int c0 = (tid & 1) * 4;      // 0 or 4
    const __half* gp[3];
    gp[0] = p.Af    + (size_t)(m0 + rA) * K + c0 * 8;
    gp[1] = p.Bh[z] + (size_t)(n0 + rA) * K + c0 * 8;
    gp[2] = p.Bl[z] + (size_t)(n0 + rA) * K + c0 * 8;
    uint32_t soff[4];
    #pragma unroll
    for (int j = 0; j < 4; j++) soff[j] = swz8(rA, c0 + j);

    const int wid = tid >> 5, lane = tid & 31;
    const int wm = (wid & 1) * 64;
    const int wn = (wid >> 1) * 32;

    // ---- fragment base offsets (swizzled); kh step = XOR (kh<<5) ----
    const int rowa = wm + (lane & 15);
    const uint32_t aSw = swz8(rowa, (lane >> 4) & 1);
    const int rowb = wn + (lane & 7) + ((lane >> 4) << 3);
    const uint32_t bSw = (uint32_t)TILE_BYTES + swz8(rowb, (lane >> 3) & 1);

    float acc[4][4][4];
    #pragma unroll
    for (int a = 0; a < 4; a++)
        #pragma unroll
        for (int b = 0; b < 4; b++)
            #pragma unroll
            for (int c = 0; c < 4; c++) acc[a][b][c] = 0.f;

    const int nt = K >> 6;

    auto load_stage = [&](int slot, int k0) {
        uint32_t sb = sbase + (uint32_t)slot * STAGE_BYTES;
        #pragma unroll
        for (int op = 0; op < 3; op++)
            #pragma unroll
            for (int j = 0; j < 4; j++) {
                asm volatile("cp.async.cg.shared.global [%0], [%1], 16;"
                    :: "r"(sb + (uint32_t)(op * TILE_BYTES) + soff[j]),
                       "l"(gp[op] + k0 + j * 8));
            }
        asm volatile("cp.async.commit_group;" ::: "memory");
    };

    load_stage(0, 0);
    load_stage(1, 64);

    for (int t = 0; t < nt; t++) {
        if (t + 1 < nt) asm volatile("cp.async.wait_group 1;" ::: "memory");
        else            asm volatile("cp.async.wait_group 0;" ::: "memory");
        __syncthreads();

        const uint32_t stg = sbase + (uint32_t)(t & 1) * STAGE_BYTES;
        #pragma unroll
        for (int kh = 0; kh < 4; kh++) {
            const uint32_t kx = (uint32_t)(kh << 5);
            uint32_t bfr[2][2][4];
            #pragma unroll
            for (int ng = 0; ng < 2; ng++)
                #pragma unroll
                for (int sp = 0; sp < 2; sp++)
                    LDMX4(bfr[sp][ng],
                          stg + ((bSw + (uint32_t)(sp * TILE_BYTES + ng * 2048)) ^ kx));
            uint32_t afr[4][4];
            #pragma unroll
            for (int mt = 0; mt < 4; mt++)
                LDMX4(afr[mt], stg + ((aSw + (uint32_t)(mt * 2048)) ^ kx));
            // term-major: all Af*Bh, then all Af*Bl (per-acc order preserved)
            #pragma unroll
            for (int mt = 0; mt < 4; mt++)
                #pragma unroll
                for (int nn = 0; nn < 4; nn++) {
                    int ng = nn >> 1, hb = (nn & 1) * 2;
                    uint32_t b2[2] = { bfr[0][ng][hb], bfr[0][ng][hb+1] };
                    MMA_F16(acc[mt][nn], afr[mt], b2);   // Af*Bh
                }
            #pragma unroll
            for (int mt = 0; mt < 4; mt++)
                #pragma unroll
                for (int nn = 0; nn < 4; nn++) {
                    int ng = nn >> 1, hb = (nn & 1) * 2;
                    uint32_t b2[2] = { bfr[1][ng][hb], bfr[1][ng][hb+1] };
                    MMA_F16(acc[mt][nn], afr[mt], b2);   // Af*Bl
                }
        }
        __syncthreads();
        if (t + 2 < nt) load_stage(t & 1, (t + 2) * 64);
    }

    // ---- epilogue ----
    const float* bias = p.bias[z];
    const int pm = OUTH ? 0 : p.pmode[z];
    const int lenb = g_len[m0 >> 11];     // batch fixed per CTA (128 | 2048)
    #pragma unroll
    for (int nn = 0; nn < 4; nn++) {
        int cn = n0 + wn + nn * 8 + (lane & 3) * 2;
        float b0v = bias[cn], b1v = bias[cn + 1];
        #pragma unroll
        for (int mt = 0; mt < 4; mt++) {
            int r0 = m0 + wm + mt * 16 + (lane >> 2);
            #pragma unroll
            for (int half_ = 0; half_ < 2; half_++) {
                int r = r0 + half_ * 8;
                float v0 = acc[mt][nn][half_*2 + 0] + b0v;
                float v1 = acc[mt][nn][half_*2 + 1] + b1v;
                if (RELU) { v0 = fmaxf(v0, 0.f); v1 = fmaxf(v1, 0.f); }
                if (OUTH) {
                    __half2 hp;
                    hp.x = __float2half_rn(v0);
                    hp.y = __float2half_rn(v1);
                    *(__half2*)(p.outh[z] + (size_t)r * N + cn) = hp;
                } else {
                    if (pm == 1) { v0 = phi_f(v0); v1 = phi_f(v1); }
                    else if (pm == 2) {
                        if ((r & (SS - 1)) < lenb) { v0 = phi_f(v0); v1 = phi_f(v1); }
                        else { v0 = 0.f; v1 = 0.f; }
                    }
                    float2 o; o.x = v0; o.y = v1;
                    *(float2*)(p.outf[z] + (size_t)r * N + cn) = o;
                }
            }
        }
    }
}

// ---------------- attention pass 1: per-chunk  S_c = phiK^T V,  ks_c = sum phiK
// g_k already holds masked phi(k); g_v raw.
__global__ void __launch_bounds__(256) att_sums_kernel() {
    __shared__ float sK[CC][68];
    __shared__ float sV[CC][68];
    int c = blockIdx.x, bh = blockIdx.y;
    int b = bh >> 3, h = bh & 7;
    int tid = threadIdx.x;
    #pragma unroll
    for (int it = 0; it < 4; it++) {
        int idx = it * 256 + tid;            // 0..1023
        int j  = idx >> 4;                   // row 0..63
        int d4 = (idx & 15) << 2;            // 0..60
        size_t g = ((size_t)(b * SS + c * CC + j)) * DD + h * DHH + d4;
        *(float4*)&sK[j][d4] = *(const float4*)&g_k[g];
        *(float4*)&sV[j][d4] = *(const float4*)&g_v[g];
    }
    __syncthreads();
    int ti = tid & 15, tj = tid >> 4;
    float acc[4][4];
    #pragma unroll
    for (int r = 0; r < 4; r++)
        #pragma unroll
        for (int e = 0; e < 4; e++) acc[r][e] = 0.f;
    #pragma unroll 8
    for (int j = 0; j < CC; j++) {
        float4 kf = *(const float4*)&sK[j][ti*4];
        float4 vf = *(const float4*)&sV[j][tj*4];
        float ka[4] = {kf.x,kf.y,kf.z,kf.w};
        float va[4] = {vf.x,vf.y,vf.z,vf.w};
        #pragma unroll
        for (int r = 0; r < 4; r++)
            #pragma unroll
            for (int e = 0; e < 4; e++)
                acc[r][e] = fmaf(ka[r], va[e], acc[r][e]);
    }
    float* So = &g_S[((size_t)(bh * NCC + c)) * (DHH * DHH)];
    #pragma unroll
    for (int r = 0; r < 4; r++) {
        int d = ti * 4 + r;
        float4 o; o.x = acc[r][0]; o.y = acc[r][1]; o.z = acc[r][2]; o.w = acc[r][3];
        *(float4*)&So[d * DHH + tj * 4] = o;
    }
    if (tid < DHH) {
        float s = 0.f;
        #pragma unroll 8
        for (int j = 0; j < CC; j++) s += sK[j][tid];
        g_ks[(bh * NCC + c) * DHH + tid] = s;
    }
}

// ---------------- attention pass 2: exclusive prefix over chunks (parallel) -----
// grid (BHH, 8): partition the 4096 state elements into 8 blocks of 512;
// per-element sequential running sum unchanged (bit-identical).
__global__ void __launch_bounds__(256) att_scan_kernel() {
    int bh = blockIdx.x, part = blockIdx.y, tid = threadIdx.x;
    int e0 = part * 512 + tid * 2;
    float r0 = 0.f, r1 = 0.f;
    for (int c = 0; c < NCC; c++) {
        float* p = &g_S[((size_t)(bh * NCC + c)) * (DHH*DHH) + e0];
        float2 tv = *(const float2*)p;
        float2 rv; rv.x = r0; rv.y = r1;
        *(float2*)p = rv;
        r0 += tv.x; r1 += tv.y;
    }
    if (part == 0 && tid < DHH) {
        float rk = 0.f;
        for (int c = 0; c < NCC; c++) {
            float* kp = &g_ks[(bh * NCC + c) * DHH + tid];
            float t = *kp; *kp = rk; rk += t;
        }
    }
}

// ---------------- attention pass 3 ----------------
// g_q holds phi(q); g_k holds masked phi(k).
#define SM3_FLOATS (3*CC*68 + DHH)
#define SM3_BYTES  (SM3_FLOATS * 4)
__global__ void __launch_bounds__(256) att_out_kernel() {
    extern __shared__ float smf[];
    float* sQ  = smf;
    float* sKV = smf + CC*68;
    float* sSA = smf + 2*CC*68;
    float* skp = smf + 3*CC*68;

    int c = blockIdx.x, bh = blockIdx.y;
    int b = bh >> 3, h = bh & 7;
    int tid = threadIdx.x;

    const float* Sg = &g_S[((size_t)(bh * NCC + c)) * (DHH*DHH)];
    #pragma unroll
    for (int it = 0; it < 4; it++) {
        int idx = it * 256 + tid;            // 0..1023
        int r  = idx >> 4;                   // row 0..63
        int d4 = (idx & 15) << 2;            // 0..60
        size_t g = ((size_t)(b * SS + c * CC + r)) * DD + h * DHH + d4;
        float4 q4 = *(const float4*)&g_q[g];
        float4 k4 = *(const float4*)&g_k[g];
        sQ[(d4+0)*68 + r] = q4.x;
        sQ[(d4+1)*68 + r] = q4.y;
        sQ[(d4+2)*68 + r] = q4.z;
        sQ[(d4+3)*68 + r] = q4.w;
        sKV[(d4+0)*68 + r] = k4.x;
        sKV[(d4+1)*68 + r] = k4.y;
        sKV[(d4+2)*68 + r] = k4.z;
        sKV[(d4+3)*68 + r] = k4.w;
        float4 s4 = *(const float4*)&Sg[r * DHH + d4];
        *(float4*)&sSA[r*68 + d4] = s4;      // sSA[d][e] with row index = d
    }
    if (tid < DHH) skp[tid] = g_ks[(bh * NCC + c) * DHH + tid];
    __syncthreads();

    int ti = tid & 15, tj = tid >> 4;

    float zi = 0.f;
    if (tid < DHH) {
        #pragma unroll 8
        for (int d = 0; d < DHH; d++) zi += sQ[d*68 + tid] * skp[d];
    }

    float oacc[4][4], aacc[4][4];
    #pragma unroll
    for (int r = 0; r < 4; r++)
        #pragma unroll
        for (int e = 0; e < 4; e++) { oacc[r][e] = 0.f; aacc[r][e] = 0.f; }
    #pragma unroll 4
    for (int d = 0; d < DHH; d++) {
        float4 aq = *(const float4*)&sQ [d*68 + ti*4];
        float4 bs = *(const float4*)&sSA[d*68 + tj*4];
        float4 bk = *(const float4*)&sKV[d*68 + tj*4];
        float qa[4] = {aq.x,aq.y,aq.z,aq.w};
        float sa[4] = {bs.x,bs.y,bs.z,bs.w};
        float ka[4] = {bk.x,bk.y,bk.z,bk.w};
        #pragma unroll
        for (int r = 0; r < 4; r++)
            #pragma unroll
            for (int e = 0; e < 4; e++) {
                oacc[r][e] = fmaf(qa[r], sa[e], oacc[r][e]);
                aacc[r][e] = fmaf(qa[r], ka[e], aacc[r][e]);
            }
    }
    __syncthreads();

    #pragma unroll
    for (int r = 0; r < 4; r++)
        #pragma unroll
        for (int e = 0; e < 4; e++) {
            int i = ti * 4 + r, j = tj * 4 + e;
            sSA[j*68 + i] = (j <= i) ? aacc[r][e] : 0.f;
        }
    #pragma unroll
    for (int it = 0; it < 4; it++) {
        int idx = it * 256 + tid;
        int r  = idx >> 4;
        int e4 = (idx & 15) << 2;
        float4 v4 = *(const float4*)&g_v[((size_t)(b * SS + c * CC + r)) * DD + h * DHH + e4];
        *(float4*)&sKV[r*68 + e4] = v4;
    }
    __syncthreads();

    if (tid < DHH) {
        float z = zi;
        #pragma unroll 8
        for (int j = 0; j < CC; j++) z += sSA[j*68 + tid];
        skp[tid] = 1.f / (z + 1e-6f);
    }

    #pragma unroll 4
    for (int j = 0; j < CC; j++) {
        float4 aj = *(const float4*)&sSA[j*68 + ti*4];
        float4 ve = *(const float4*)&sKV[j*68 + tj*4];
        float aa[4] = {aj.x,aj.y,aj.z,aj.w};
        float va[4] = {ve.x,ve.y,ve.z,ve.w};
        #pragma unroll
        for (int r = 0; r < 4; r++)
            #pragma unroll
            for (int e = 0; e < 4; e++)
                oacc[r][e] = fmaf(aa[r], va[e], oacc[r][e]);
    }
    __syncthreads();

    #pragma unroll
    for (int r = 0; r < 4; r++) {
        int i = ti * 4 + r;
        float zr = skp[i];
        size_t base = ((size_t)(b * SS + c * CC + i)) * DD + h * DHH + tj * 4;
        #pragma unroll
        for (int e = 0; e < 4; e++) {
            float o = oacc[r][e] * zr;
            g_af[base + e] = __float2half_rn(o);
        }
    }
}

// ---------------- LayerNorm (+ residual, + optional fp16 out) ----------------
__global__ void ln_kernel(const float* __restrict__ x, const float* __restrict__ add,
                          const float* __restrict__ gamma, const float* __restrict__ beta,
                          float* __restrict__ out, __half* __restrict__ oh) {
    __shared__ float rs[4], rq[4];
    int row = blockIdx.x, tid = threadIdx.x;
    float4 v = ((const float4*)(x + (size_t)row * DD))[tid];
    if (add) {
        float4 a = ((const float4*)(add + (size_t)row * DD))[tid];
        v.x += a.x; v.y += a.y; v.z += a.z; v.w += a.w;
    }
    float s = v.x + v.y + v.z + v.w;
    float q = v.x*v.x + v.y*v.y + v.z*v.z + v.w*v.w;
    #pragma unroll
    for (int off = 16; off; off >>= 1) {
        s += __shfl_xor_sync(0xffffffffu, s, off);
        q += __shfl_xor_sync(0xffffffffu, q, off);
    }
    if ((tid & 31) == 0) { rs[tid >> 5] = s; rq[tid >> 5] = q; }
    __syncthreads();
    s = rs[0] + rs[1] + rs[2] + rs[3];
    q = rq[0] + rq[1] + rq[2] + rq[3];
    float mu   = s * (1.f / DD);
    float var  = q * (1.f / DD) - mu * mu;
    float rstd = rsqrtf(var + 1e-5f);
    float4 g  = ((const float4*)gamma)[tid];
    float4 bt = ((const float4*)beta)[tid];
    float4 o;
    o.x = (v.x - mu) * rstd * g.x + bt.x;
    o.y = (v.y - mu) * rstd * g.y + bt.y;
    o.z = (v.z - mu) * rstd * g.z + bt.z;
    o.w = (v.w - mu) * rstd * g.w + bt.w;
    ((float4*)(out + (size_t)row * DD))[tid] = o;
    if (oh) {
        size_t e0 = (size_t)row * DD + tid * 4;
        oh[e0+0] = __float2half_rn(o.x);
        oh[e0+1] = __float2half_rn(o.y);
        oh[e0+2] = __float2half_rn(o.z);
        oh[e0+3] = __float2half_rn(o.w);
    }
}

// ---------------- launch --------------------------------------------------------
extern "C" void kernel_launch(void* const* d_in, const int* in_sizes, int n_in,
                              void* d_out, int out_size) {
    (void)in_sizes; (void)n_in; (void)out_size;
    const int*   x   = (const int*)  d_in[0];
    const float* emb = (const float*)d_in[1];
    const float* pe  = (const float*)d_in[2];
    const float* Wq  = (const float*)d_in[3];
    const float* bq  = (const float*)d_in[4];
    const float* Wk  = (const float*)d_in[5];
    const float* bk  = (const float*)d_in[6];
    const float* Wv  = (const float*)d_in[7];
    const float* bv  = (const float*)d_in[8];
    const float* Wo  = (const float*)d_in[9];
    const float* bo  = (const float*)d_in[10];
    const float* W1  = (const float*)d_in[11];
    const float* b1  = (const float*)d_in[12];
    const float* W2  = (const float*)d_in[13];
    const float* b2  = (const float*)d_in[14];
    const float* g1  = (const float*)d_in[15];
    const float* be1 = (const float*)d_in[16];
    const float* g2  = (const float*)d_in[17];
    const float* be2 = (const float*)d_in[18];
    const float* gf  = (const float*)d_in[19];
    const float* bf  = (const float*)d_in[20];

    float *h, *q, *kk, *vv;
    cudaGetSymbolAddress((void**)&h, g_h);
    cudaGetSymbolAddress((void**)&q, g_q);
    cudaGetSymbolAddress((void**)&kk, g_k);
    cudaGetSymbolAddress((void**)&vv, g_v);
    __half *hf, *af, *tf;
    cudaGetSymbolAddress((void**)&hf, g_hf);
    cudaGetSymbolAddress((void**)&af, g_af);
    cudaGetSymbolAddress((void**)&tf, g_tf);
    __half *wqh, *wql, *wkh, *wkl, *wvh, *wvl, *woh, *wol, *w1h, *w1l, *w2h, *w2l;
    cudaGetSymbolAddress((void**)&wqh, g_wq_h); cudaGetSymbolAddress((void**)&wql, g_wq_l);
    cudaGetSymbolAddress((void**)&wkh, g_wk_h); cudaGetSymbolAddress((void**)&wkl, g_wk_l);
    cudaGetSymbolAddress((void**)&wvh, g_wv_h); cudaGetSymbolAddress((void**)&wvl, g_wv_l);
    cudaGetSymbolAddress((void**)&woh, g_wo_h); cudaGetSymbolAddress((void**)&wol, g_wo_l);
    cudaGetSymbolAddress((void**)&w1h, g_w1_h); cudaGetSymbolAddress((void**)&w1l, g_w1_l);
    cudaGetSymbolAddress((void**)&w2h, g_w2_h); cudaGetSymbolAddress((void**)&w2l, g_w2_l);

    cudaFuncSetAttribute(att_out_kernel,
                         cudaFuncAttributeMaxDynamicSharedMemorySize, SM3_BYTES);
    cudaFuncSetAttribute(gemm_mma<0,0>,
                         cudaFuncAttributeMaxDynamicSharedMemorySize, GM_SMEM_BYTES);
    cudaFuncSetAttribute(gemm_mma<1,1>,
                         cudaFuncAttributeMaxDynamicSharedMemorySize, GM_SMEM_BYTES);

    len_kernel<<<BB, 256>>>(x);
    embed_kernel<<<(MM * (DD/4) + 255) / 256, 256>>>(x, emb, pe);

    // batched weight transpose+split: 24 matrices, one launch
    {
        WtcArgs wa = {};
        int idx = 0;
        for (int l = 0; l < NLL; l++) {
            size_t wo = (size_t)l * DD * DD;
            size_t wf = (size_t)l * DD * FF;
            wa.src[idx] = Wq + wo; wa.oh[idx] = wqh + wo; wa.ol[idx] = wql + wo; wa.K[idx] = DD; wa.N[idx] = DD; idx++;
            wa.src[idx] = Wk + wo; wa.oh[idx] = wkh + wo; wa.ol[idx] = wkl + wo; wa.K[idx] = DD; wa.N[idx] = DD; idx++;
            wa.src[idx] = Wv + wo; wa.oh[idx] = wvh + wo; wa.ol[idx] = wvl + wo; wa.K[idx] = DD; wa.N[idx] = DD; idx++;
            wa.src[idx] = Wo + wo; wa.oh[idx] = woh + wo; wa.ol[idx] = wol + wo; wa.K[idx] = DD; wa.N[idx] = DD; idx++;
            wa.src[idx] = W1 + wf; wa.oh[idx] = w1h + wf; wa.ol[idx] = w1l + wf; wa.K[idx] = DD; wa.N[idx] = FF; idx++;
            wa.src[idx] = W2 + wf; wa.oh[idx] = w2h + wf; wa.ol[idx] = w2l + wf; wa.K[idx] = FF; wa.N[idx] = DD; idx++;
        }
        wtc_all_kernel<<<dim3(FF/32, FF/32, 24), dim3(32, 8)>>>(wa);
    }

    for (int l = 0; l < NLL; l++) {
        size_t wo   = (size_t)l * DD * DD;
        size_t wf   = (size_t)l * DD * FF;
        size_t boff = (size_t)l * DD;

        // QKV fused; epilogue applies phi (q), masked phi (k)
        GTArgs ga = {};
        ga.Af = hf; ga.N = DD; ga.K = DD;
        ga.Bh[0] = wqh + wo; ga.Bl[0] = wql + wo;
        ga.Bh[1] = wkh + wo; ga.Bl[1] = wkl + wo;
        ga.Bh[2] = wvh + wo; ga.Bl[2] = wvl + wo;
        ga.bias[0] = bq + boff; ga.bias[1] = bk + boff; ga.bias[2] = bv + boff;
        ga.outf[0] = q; ga.outf[1] = kk; ga.outf[2] = vv;
        ga.pmode[0] = 1; ga.pmode[1] = 2; ga.pmode[2] = 0;
        gemm_mma<0,0><<<dim3(DD/128, MM/128, 3), 256, GM_SMEM_BYTES>>>(ga);

        att_sums_kernel<<<dim3(NCC, BHH), 256>>>();
        att_scan_kernel<<<dim3(BHH, 8), 256>>>();
        att_out_kernel<<<dim3(NCC, BHH), 256, SM3_BYTES>>>();

        // O proj
        GTArgs go = {};
        go.Af = af; go.N = DD; go.K = DD;
        go.Bh[0] = woh + wo; go.Bl[0] = wol + wo;
        go.bias[0] = bo + boff; go.outf[0] = q;
        gemm_mma<0,0><<<dim3(DD/128, MM/128, 1), 256, GM_SMEM_BYTES>>>(go);

        ln_kernel<<<MM, 128>>>(h, q, g1 + boff, be1 + boff, h, hf);

        // FFN1 (relu, fp16 output)
        GTArgs g1a = {};
        g1a.Af = hf; g1a.N = FF; g1a.K = DD;
        g1a.Bh[0] = w1h + wf; g1a.Bl[0] = w1l + wf;
        g1a.bias[0] = b1 + (size_t)l * FF;
        g1a.outh[0] = tf;
        gemm_mma<1,1><<<dim3(FF/128, MM/128, 1), 256, GM_SMEM_BYTES>>>(g1a);

        // FFN2
        GTArgs g2a = {};
        g2a.Af = tf; g2a.N = DD; g2a.K = FF;
        g2a.Bh[0] = w2h + wf; g2a.Bl[0] = w2l + wf;
        g2a.bias[0] = b2 + boff; g2a.outf[0] = q;
        gemm_mma<0,0><<<dim3(DD/128, MM/128, 1), 256, GM_SMEM_BYTES>>>(g2a);

        ln_kernel<<<MM, 128>>>(h, q, g2 + boff, be2 + boff, h, hf);
    }

    ln_kernel<<<MM, 128>>>(h, nullptr, gf, bf, (float*)d_out, nullptr);
}

// round 13
// speedup vs baseline: 1.1402x; 1.1402x over previous
#include <cuda_runtime.h>
#include <cuda_fp16.h>
#include <cstdint>

// ---------------- problem constants ----------------
#define BB  4
#define SS  2048
#define DD  512
#define HH  8
#define DHH 64
#define FF  2048
#define NLL 4
#define MM  (BB*SS)      // 8192 rows
#define CC  64           // attention chunk length
#define NCC (SS/CC)      // 32 chunks
#define BHH (BB*HH)      // 32 (b,h) pairs

__device__ __forceinline__ uint32_t smem_u32(const void* p) {
    uint32_t a;
    asm("{ .reg .u64 t; cvta.to.shared.u64 t, %1; cvt.u32.u64 %0, t; }" : "=r"(a) : "l"(p));
    return a;
}

// ---------------- scratch (device globals; no allocs allowed) ----------------
__device__ float g_h[MM*DD];
__device__ float g_q[MM*DD];          // holds phi(q) after QKV
__device__ float g_k[MM*DD];          // holds masked phi(k) after QKV
__device__ float g_v[MM*DD];
__device__ float g_S[(size_t)BHH*NCC*DHH*DHH];
__device__ float g_ks[BHH*NCC*DHH];
__device__ int   g_len[BB];

// fp16 activations (single-rounded)
__device__ __align__(16) __half g_hf[MM*DD];             // residual stream as GEMM-A
__device__ __align__(16) __half g_af[MM*DD];             // attention output
__device__ __align__(16) __half g_tf[(size_t)MM*FF];     // FFN hidden

// transposed weights as fp16 hi/lo pairs: layout [N][K]
__device__ __align__(16) __half g_wq_h[NLL*DD*DD], g_wq_l[NLL*DD*DD];
__device__ __align__(16) __half g_wk_h[NLL*DD*DD], g_wk_l[NLL*DD*DD];
__device__ __align__(16) __half g_wv_h[NLL*DD*DD], g_wv_l[NLL*DD*DD];
__device__ __align__(16) __half g_wo_h[NLL*DD*DD], g_wo_l[NLL*DD*DD];
__device__ __align__(16) __half g_w1_h[NLL*FF*DD], g_w1_l[NLL*FF*DD];
__device__ __align__(16) __half g_w2_h[NLL*DD*FF], g_w2_l[NLL*DD*FF];

__device__ __forceinline__ float phi_f(float u) { return u > 0.f ? u + 1.f : __expf(u); }

__device__ __forceinline__ void split_h(float x, __half& h, __half& l) {
    h = __float2half_rn(x);
    l = __float2half_rn(x - __half2float(h));
}

// ---------------- lengths ----------------
__global__ void len_kernel(const int* __restrict__ x) {
    __shared__ int red[256];
    int b = blockIdx.x, tid = threadIdx.x;
    int cnt = 0;
    for (int s = tid; s < SS; s += 256) cnt += (x[b*SS + s] != 0);
    red[tid] = cnt; __syncthreads();
    for (int off = 128; off; off >>= 1) {
        if (tid < off) red[tid] += red[tid + off];
        __syncthreads();
    }
    if (tid == 0) g_len[b] = red[0];
}

// ---------------- embedding + positional (+ fp16 round) ----------------
__global__ void embed_kernel(const int* __restrict__ x,
                             const float* __restrict__ emb,
                             const float* __restrict__ pe) {
    int idx = blockIdx.x * 256 + threadIdx.x;
    if (idx >= MM * (DD/4)) return;
    int i  = idx >> 7;
    int d4 = idx & 127;
    int s  = i & (SS - 1);
    int tok = x[i];
    float4 e = ((const float4*)emb)[(size_t)tok * (DD/4) + d4];
    float4 p = ((const float4*)pe)[(size_t)s * (DD/4) + d4];
    float4 o;
    o.x = e.x + p.x; o.y = e.y + p.y; o.z = e.z + p.z; o.w = e.w + p.w;
    ((float4*)g_h)[idx] = o;
    size_t e0 = (size_t)idx * 4;
    g_hf[e0+0] = __float2half_rn(o.x);
    g_hf[e0+1] = __float2half_rn(o.y);
    g_hf[e0+2] = __float2half_rn(o.z);
    g_hf[e0+3] = __float2half_rn(o.w);
}

// ---------------- batched weight transpose + split (24 matrices, one launch) ----
struct WtcArgs {
    const float* src[24];
    __half* oh[24];
    __half* ol[24];
    int K[24], N[24];
};
__global__ void wtc_all_kernel(WtcArgs p) {
    __shared__ float t[32][33];
    int m = blockIdx.z;
    int K = p.K[m], N = p.N[m];
    int n0 = blockIdx.x * 32, k0 = blockIdx.y * 32;
    if (n0 >= N || k0 >= K) return;
    const float* W = p.src[m];
    __half *oh = p.oh[m], *ol = p.ol[m];
    int tx = threadIdx.x, ty = threadIdx.y;   // 32x8
    #pragma unroll
    for (int i = 0; i < 32; i += 8)
        t[ty + i][tx] = W[(size_t)(k0 + ty + i) * N + n0 + tx];
    __syncthreads();
    #pragma unroll
    for (int i = 0; i < 32; i += 8) {
        float v = t[tx][ty + i];
        size_t o = (size_t)(n0 + ty + i) * K + k0 + tx;
        split_h(v, oh[o], ol[o]);
    }
}

// ---------------- 2-term fp16 GEMM via warp mma.sync (Round-10 config) ----------
// C[M,N] = A[M,K] * B[N,K]^T + bias ; A single fp16, B as fp16 (hi,lo) pair.
// C = Af*Bh + Af*Bl.  Block 128x128, BK=32, 256 thr, warp tile 64x32.
// 4-stage cp.async pipeline, swizzled 64B-pitch smem, one sync/iter, 2 CTAs/SM.
// pmode (float-out path): 0=none, 1=phi, 2=masked phi.
struct GTArgs {
    const __half *Af;
    const __half *Bh[3], *Bl[3];
    const float* bias[3];
    float* outf[3];
    __half* outh[3];
    int pmode[3];
    int N, K;
};

#define STAGES 4
#define TILE_BYTES 8192                    // 128 rows x 64B (swizzled)
#define STAGE_BYTES (3*TILE_BYTES)         // Af,Bh,Bl = 24576
#define GM_SMEM_BYTES (STAGES*STAGE_BYTES) // 98304

// swizzled in-tile byte offset for (row, 16B-chunk c): row*64 + (c ^ ((row>>1)&3))*16
__device__ __forceinline__ uint32_t swz(int row, int c) {
    return (uint32_t)(row * 64 + ((c ^ ((row >> 1) & 3)) << 4));
}

#define MMA_F16(d, a, b) \
    asm volatile("mma.sync.aligned.m16n8k16.row.col.f32.f16.f16.f32 " \
        "{%0,%1,%2,%3}, {%4,%5,%6,%7}, {%8,%9}, {%0,%1,%2,%3};" \
        : "+f"((d)[0]), "+f"((d)[1]), "+f"((d)[2]), "+f"((d)[3]) \
        : "r"((a)[0]), "r"((a)[1]), "r"((a)[2]), "r"((a)[3]), "r"((b)[0]), "r"((b)[1]))

#define LDMX4(r, addr) \
    asm volatile("ldmatrix.sync.aligned.m8n8.x4.shared.b16 {%0,%1,%2,%3}, [%4];" \
        : "=r"((r)[0]), "=r"((r)[1]), "=r"((r)[2]), "=r"((r)[3]) : "r"(addr))

template<int RELU, int OUTH>
__global__ void __launch_bounds__(256, 2) gemm_mma(GTArgs p) {
    extern __shared__ __half sm[];
    const uint32_t sbase = smem_u32(sm);
    const int z = blockIdx.z;
    const int N = p.N, K = p.K;
    const int tid = threadIdx.x;
    const int m0 = blockIdx.y * 128, n0 = blockIdx.x * 128;

    // ---- loader: each thread owns (row rA, chunk chk); 6 x 16B per stage
    const int rA  = tid >> 2;          // 0..63
    const int chk = tid & 3;           // 16B chunk within 64B row
    const __half* gp[3];
    gp[0] = p.Af    + (size_t)(m0 + rA) * K + chk * 8;
    gp[1] = p.Bh[z] + (size_t)(n0 + rA) * K + chk * 8;
    gp[2] = p.Bl[z] + (size_t)(n0 + rA) * K + chk * 8;
    const uint32_t s0 = swz(rA, chk);  // rows rA and rA+64 share swizzle bits
    const size_t K64 = (size_t)K << 6; // 64 rows of stride K

    const int wid = tid >> 5, lane = tid & 31;
    const int wm = (wid & 1) * 64;
    const int wn = (wid >> 1) * 32;

    // ---- fragment base offsets (swizzled); kh step = XOR 0x20 ----
    const int rowa = wm + (lane & 15);
    const uint32_t aSw = swz(rowa, (lane >> 4) & 1);
    const int rowb = wn + (lane & 7) + ((lane >> 4) << 3);
    const uint32_t bSw = (uint32_t)TILE_BYTES + swz(rowb, (lane >> 3) & 1);

    float acc[4][4][4];
    #pragma unroll
    for (int a = 0; a < 4; a++)
        #pragma unroll
        for (int b = 0; b < 4; b++)
            #pragma unroll
            for (int c = 0; c < 4; c++) acc[a][b][c] = 0.f;

    const int nt = K >> 5;

    auto load_stage = [&](int slot, int k0) {
        uint32_t sb = sbase + (uint32_t)slot * STAGE_BYTES + s0;
        #pragma unroll
        for (int op = 0; op < 3; op++)
            #pragma unroll
            for (int j = 0; j < 2; j++) {
                asm volatile("cp.async.cg.shared.global [%0], [%1], 16;"
                    :: "r"(sb + (uint32_t)(op * TILE_BYTES + j * 4096)),
                       "l"(gp[op] + (j ? K64 : 0) + k0));
            }
        asm volatile("cp.async.commit_group;" ::: "memory");
    };

    // prologue: 3 stages in flight
    load_stage(0, 0);
    load_stage(1, 32);
    load_stage(2, 64);

    int cslot = 0, lslot = 3;
    for (int t = 0; t < nt; t++) {
        asm volatile("cp.async.wait_group 2;" ::: "memory");
        __syncthreads();
        if (t + 3 < nt) load_stage(lslot, (t + 3) * 32);
        else asm volatile("cp.async.commit_group;" ::: "memory");
        if (++lslot == STAGES) lslot = 0;

        const uint32_t stg = sbase + (uint32_t)cslot * STAGE_BYTES;
        if (++cslot == STAGES) cslot = 0;
        #pragma unroll
        for (int kh = 0; kh < 2; kh++) {
            const uint32_t kx = (uint32_t)(kh * 0x20);   // chunk+2 under swizzle
            // B fragments first (4 loads: Bh,Bl x 2 ng), then A (4 loads).
            uint32_t bfr[2][2][4];
            #pragma unroll
            for (int ng = 0; ng < 2; ng++)
                #pragma unroll
                for (int sp = 0; sp < 2; sp++)
                    LDMX4(bfr[sp][ng],
                          stg + ((bSw + (uint32_t)(sp * TILE_BYTES + ng * 1024)) ^ kx));
            uint32_t afr[4][4];
            #pragma unroll
            for (int mt = 0; mt < 4; mt++)
                LDMX4(afr[mt],
                      stg + ((aSw + (uint32_t)(mt * 1024)) ^ kx));
            // term-major: all Af*Bh, then all Af*Bl (per-acc order preserved).
            #pragma unroll
            for (int mt = 0; mt < 4; mt++)
                #pragma unroll
                for (int nn = 0; nn < 4; nn++) {
                    int ng = nn >> 1, hb = (nn & 1) * 2;
                    uint32_t b0h[2] = { bfr[0][ng][hb], bfr[0][ng][hb+1] };
                    MMA_F16(acc[mt][nn], afr[mt], b0h);  // Af*Bh
                }
            #pragma unroll
            for (int mt = 0; mt < 4; mt++)
                #pragma unroll
                for (int nn = 0; nn < 4; nn++) {
                    int ng = nn >> 1, hb = (nn & 1) * 2;
                    uint32_t b0l[2] = { bfr[1][ng][hb], bfr[1][ng][hb+1] };
                    MMA_F16(acc[mt][nn], afr[mt], b0l);  // Af*Bl
                }
        }
    }

    // ---- epilogue ----
    const float* bias = p.bias[z];
    const int pm = OUTH ? 0 : p.pmode[z];
    const int lenb = g_len[m0 >> 11];     // batch fixed per CTA (128 | 2048)
    #pragma unroll
    for (int nn = 0; nn < 4; nn++) {
        int cn = n0 + wn + nn * 8 + (lane & 3) * 2;
        float b0v = bias[cn], b1v = bias[cn + 1];
        #pragma unroll
        for (int mt = 0; mt < 4; mt++) {
            int r0 = m0 + wm + mt * 16 + (lane >> 2);
            #pragma unroll
            for (int half_ = 0; half_ < 2; half_++) {
                int r = r0 + half_ * 8;
                float v0 = acc[mt][nn][half_*2 + 0] + b0v;
                float v1 = acc[mt][nn][half_*2 + 1] + b1v;
                if (RELU) { v0 = fmaxf(v0, 0.f); v1 = fmaxf(v1, 0.f); }
                if (OUTH) {
                    __half2 hp;
                    hp.x = __float2half_rn(v0);
                    hp.y = __float2half_rn(v1);
                    *(__half2*)(p.outh[z] + (size_t)r * N + cn) = hp;
                } else {
                    if (pm == 1) { v0 = phi_f(v0); v1 = phi_f(v1); }
                    else if (pm == 2) {
                        if ((r & (SS - 1)) < lenb) { v0 = phi_f(v0); v1 = phi_f(v1); }
                        else { v0 = 0.f; v1 = 0.f; }
                    }
                    float2 o; o.x = v0; o.y = v1;
                    *(float2*)(p.outf[z] + (size_t)r * N + cn) = o;
                }
            }
        }
    }
}

// ---------------- attention pass 1: per-chunk  S_c = phiK^T V,  ks_c = sum phiK
// g_k already holds masked phi(k); g_v raw.
__global__ void __launch_bounds__(256) att_sums_kernel() {
    __shared__ float sK[CC][68];
    __shared__ float sV[CC][68];
    int c = blockIdx.x, bh = blockIdx.y;
    int b = bh >> 3, h = bh & 7;
    int tid = threadIdx.x;
    #pragma unroll
    for (int it = 0; it < 4; it++) {
        int idx = it * 256 + tid;            // 0..1023
        int j  = idx >> 4;                   // row 0..63
        int d4 = (idx & 15) << 2;            // 0..60
        size_t g = ((size_t)(b * SS + c * CC + j)) * DD + h * DHH + d4;
        *(float4*)&sK[j][d4] = *(const float4*)&g_k[g];
        *(float4*)&sV[j][d4] = *(const float4*)&g_v[g];
    }
    __syncthreads();
    int ti = tid & 15, tj = tid >> 4;
    float acc[4][4];
    #pragma unroll
    for (int r = 0; r < 4; r++)
        #pragma unroll
        for (int e = 0; e < 4; e++) acc[r][e] = 0.f;
    #pragma unroll 8
    for (int j = 0; j < CC; j++) {
        float4 kf = *(const float4*)&sK[j][ti*4];
        float4 vf = *(const float4*)&sV[j][tj*4];
        float ka[4] = {kf.x,kf.y,kf.z,kf.w};
        float va[4] = {vf.x,vf.y,vf.z,vf.w};
        #pragma unroll
        for (int r = 0; r < 4; r++)
            #pragma unroll
            for (int e = 0; e < 4; e++)
                acc[r][e] = fmaf(ka[r], va[e], acc[r][e]);
    }
    float* So = &g_S[((size_t)(bh * NCC + c)) * (DHH * DHH)];
    #pragma unroll
    for (int r = 0; r < 4; r++) {
        int d = ti * 4 + r;
        float4 o; o.x = acc[r][0]; o.y = acc[r][1]; o.z = acc[r][2]; o.w = acc[r][3];
        *(float4*)&So[d * DHH + tj * 4] = o;
    }
    if (tid < DHH) {
        float s = 0.f;
        #pragma unroll 8
        for (int j = 0; j < CC; j++) s += sK[j][tid];
        g_ks[(bh * NCC + c) * DHH + tid] = s;
    }
}

// ---------------- attention pass 2: exclusive prefix over chunks (parallel) -----
// grid (BHH, 8): partition the 4096 state elements into 8 blocks of 512;
// per-element sequential running sum unchanged (bit-identical).
__global__ void __launch_bounds__(256) att_scan_kernel() {
    int bh = blockIdx.x, part = blockIdx.y, tid = threadIdx.x;
    int e0 = part * 512 + tid * 2;
    float r0 = 0.f, r1 = 0.f;
    for (int c = 0; c < NCC; c++) {
        float* p = &g_S[((size_t)(bh * NCC + c)) * (DHH*DHH) + e0];
        float2 tv = *(const float2*)p;
        float2 rv; rv.x = r0; rv.y = r1;
        *(float2*)p = rv;
        r0 += tv.x; r1 += tv.y;
    }
    if (part == 0 && tid < DHH) {
        float rk = 0.f;
        for (int c = 0; c < NCC; c++) {
            float* kp = &g_ks[(bh * NCC + c) * DHH + tid];
            float t = *kp; *kp = rk; rk += t;
        }
    }
}

// ---------------- attention pass 3 ----------------
// g_q holds phi(q); g_k holds masked phi(k).
#define SM3_FLOATS (3*CC*68 + DHH)
#define SM3_BYTES  (SM3_FLOATS * 4)
__global__ void __launch_bounds__(256) att_out_kernel() {
    extern __shared__ float smf[];
    float* sQ  = smf;
    float* sKV = smf + CC*68;
    float* sSA = smf + 2*CC*68;
    float* skp = smf + 3*CC*68;

    int c = blockIdx.x, bh = blockIdx.y;
    int b = bh >> 3, h = bh & 7;
    int tid = threadIdx.x;

    const float* Sg = &g_S[((size_t)(bh * NCC + c)) * (DHH*DHH)];
    #pragma unroll
    for (int it = 0; it < 4; it++) {
        int idx = it * 256 + tid;            // 0..1023
        int r  = idx >> 4;                   // row 0..63
        int d4 = (idx & 15) << 2;            // 0..60
        size_t g = ((size_t)(b * SS + c * CC + r)) * DD + h * DHH + d4;
        float4 q4 = *(const float4*)&g_q[g];
        float4 k4 = *(const float4*)&g_k[g];
        sQ[(d4+0)*68 + r] = q4.x;
        sQ[(d4+1)*68 + r] = q4.y;
        sQ[(d4+2)*68 + r] = q4.z;
        sQ[(d4+3)*68 + r] = q4.w;
        sKV[(d4+0)*68 + r] = k4.x;
        sKV[(d4+1)*68 + r] = k4.y;
        sKV[(d4+2)*68 + r] = k4.z;
        sKV[(d4+3)*68 + r] = k4.w;
        float4 s4 = *(const float4*)&Sg[r * DHH + d4];
        *(float4*)&sSA[r*68 + d4] = s4;      // sSA[d][e] with row index = d
    }
    if (tid < DHH) skp[tid] = g_ks[(bh * NCC + c) * DHH + tid];
    __syncthreads();

    int ti = tid & 15, tj = tid >> 4;

    float zi = 0.f;
    if (tid < DHH) {
        #pragma unroll 8
        for (int d = 0; d < DHH; d++) zi += sQ[d*68 + tid] * skp[d];
    }

    float oacc[4][4], aacc[4][4];
    #pragma unroll
    for (int r = 0; r < 4; r++)
        #pragma unroll
        for (int e = 0; e < 4; e++) { oacc[r][e] = 0.f; aacc[r][e] = 0.f; }
    #pragma unroll 4
    for (int d = 0; d < DHH; d++) {
        float4 aq = *(const float4*)&sQ [d*68 + ti*4];
        float4 bs = *(const float4*)&sSA[d*68 + tj*4];
        float4 bk = *(const float4*)&sKV[d*68 + tj*4];
        float qa[4] = {aq.x,aq.y,aq.z,aq.w};
        float sa[4] = {bs.x,bs.y,bs.z,bs.w};
        float ka[4] = {bk.x,bk.y,bk.z,bk.w};
        #pragma unroll
        for (int r = 0; r < 4; r++)
            #pragma unroll
            for (int e = 0; e < 4; e++) {
                oacc[r][e] = fmaf(qa[r], sa[e], oacc[r][e]);
                aacc[r][e] = fmaf(qa[r], ka[e], aacc[r][e]);
            }
    }
    __syncthreads();

    #pragma unroll
    for (int r = 0; r < 4; r++)
        #pragma unroll
        for (int e = 0; e < 4; e++) {
            int i = ti * 4 + r, j = tj * 4 + e;
            sSA[j*68 + i] = (j <= i) ? aacc[r][e] : 0.f;
        }
    #pragma unroll
    for (int it = 0; it < 4; it++) {
        int idx = it * 256 + tid;
        int r  = idx >> 4;
        int e4 = (idx & 15) << 2;
        float4 v4 = *(const float4*)&g_v[((size_t)(b * SS + c * CC + r)) * DD + h * DHH + e4];
        *(float4*)&sKV[r*68 + e4] = v4;
    }
    __syncthreads();

    if (tid < DHH) {
        float z = zi;
        #pragma unroll 8
        for (int j = 0; j < CC; j++) z += sSA[j*68 + tid];
        skp[tid] = 1.f / (z + 1e-6f);
    }

    #pragma unroll 4
    for (int j = 0; j < CC; j++) {
        float4 aj = *(const float4*)&sSA[j*68 + ti*4];
        float4 ve = *(const float4*)&sKV[j*68 + tj*4];
        float aa[4] = {aj.x,aj.y,aj.z,aj.w};
        float va[4] = {ve.x,ve.y,ve.z,ve.w};
        #pragma unroll
        for (int r = 0; r < 4; r++)
            #pragma unroll
            for (int e = 0; e < 4; e++)
                oacc[r][e] = fmaf(aa[r], va[e], oacc[r][e]);
    }
    __syncthreads();

    #pragma unroll
    for (int r = 0; r < 4; r++) {
        int i = ti * 4 + r;
        float zr = skp[i];
        size_t base = ((size_t)(b * SS + c * CC + i)) * DD + h * DHH + tj * 4;
        #pragma unroll
        for (int e = 0; e < 4; e++) {
            float o = oacc[r][e] * zr;
            g_af[base + e] = __float2half_rn(o);
        }
    }
}

// ---------------- LayerNorm (+ residual, + optional fp16 out) ----------------
__global__ void ln_kernel(const float* __restrict__ x, const float* __restrict__ add,
                          const float* __restrict__ gamma, const float* __restrict__ beta,
                          float* __restrict__ out, __half* __restrict__ oh) {
    __shared__ float rs[4], rq[4];
    int row = blockIdx.x, tid = threadIdx.x;
    float4 v = ((const float4*)(x + (size_t)row * DD))[tid];
    if (add) {
        float4 a = ((const float4*)(add + (size_t)row * DD))[tid];
        v.x += a.x; v.y += a.y; v.z += a.z; v.w += a.w;
    }
    float s = v.x + v.y + v.z + v.w;
    float q = v.x*v.x + v.y*v.y + v.z*v.z + v.w*v.w;
    #pragma unroll
    for (int off = 16; off; off >>= 1) {
        s += __shfl_xor_sync(0xffffffffu, s, off);
        q += __shfl_xor_sync(0xffffffffu, q, off);
    }
    if ((tid & 31) == 0) { rs[tid >> 5] = s; rq[tid >> 5] = q; }
    __syncthreads();
    s = rs[0] + rs[1] + rs[2] + rs[3];
    q = rq[0] + rq[1] + rq[2] + rq[3];
    float mu   = s * (1.f / DD);
    float var  = q * (1.f / DD) - mu * mu;
    float rstd = rsqrtf(var + 1e-5f);
    float4 g  = ((const float4*)gamma)[tid];
    float4 bt = ((const float4*)beta)[tid];
    float4 o;
    o.x = (v.x - mu) * rstd * g.x + bt.x;
    o.y = (v.y - mu) * rstd * g.y + bt.y;
    o.z = (v.z - mu) * rstd * g.z + bt.z;
    o.w = (v.w - mu) * rstd * g.w + bt.w;
    ((float4*)(out + (size_t)row * DD))[tid] = o;
    if (oh) {
        size_t e0 = (size_t)row * DD + tid * 4;
        oh[e0+0] = __float2half_rn(o.x);
        oh[e0+1] = __float2half_rn(o.y);
        oh[e0+2] = __float2half_rn(o.z);
        oh[e0+3] = __float2half_rn(o.w);
    }
}

// ---------------- launch --------------------------------------------------------
extern "C" void kernel_launch(void* const* d_in, const int* in_sizes, int n_in,
                              void* d_out, int out_size) {
    (void)in_sizes; (void)n_in; (void)out_size;
    const int*   x   = (const int*)  d_in[0];
    const float* emb = (const float*)d_in[1];
    const float* pe  = (const float*)d_in[2];
    const float* Wq  = (const float*)d_in[3];
    const float* bq  = (const float*)d_in[4];
    const float* Wk  = (const float*)d_in[5];
    const float* bk  = (const float*)d_in[6];
    const float* Wv  = (const float*)d_in[7];
    const float* bv  = (const float*)d_in[8];
    const float* Wo  = (const float*)d_in[9];
    const float* bo  = (const float*)d_in[10];
    const float* W1  = (const float*)d_in[11];
    const float* b1  = (const float*)d_in[12];
    const float* W2  = (const float*)d_in[13];
    const float* b2  = (const float*)d_in[14];
    const float* g1  = (const float*)d_in[15];
    const float* be1 = (const float*)d_in[16];
    const float* g2  = (const float*)d_in[17];
    const float* be2 = (const float*)d_in[18];
    const float* gf  = (const float*)d_in[19];
    const float* bf  = (const float*)d_in[20];

    float *h, *q, *kk, *vv;
    cudaGetSymbolAddress((void**)&h, g_h);
    cudaGetSymbolAddress((void**)&q, g_q);
    cudaGetSymbolAddress((void**)&kk, g_k);
    cudaGetSymbolAddress((void**)&vv, g_v);
    __half *hf, *af, *tf;
    cudaGetSymbolAddress((void**)&hf, g_hf);
    cudaGetSymbolAddress((void**)&af, g_af);
    cudaGetSymbolAddress((void**)&tf, g_tf);
    __half *wqh, *wql, *wkh, *wkl, *wvh, *wvl, *woh, *wol, *w1h, *w1l, *w2h, *w2l;
    cudaGetSymbolAddress((void**)&wqh, g_wq_h); cudaGetSymbolAddress((void**)&wql, g_wq_l);
    cudaGetSymbolAddress((void**)&wkh, g_wk_h); cudaGetSymbolAddress((void**)&wkl, g_wk_l);
    cudaGetSymbolAddress((void**)&wvh, g_wv_h); cudaGetSymbolAddress((void**)&wvl, g_wv_l);
    cudaGetSymbolAddress((void**)&woh, g_wo_h); cudaGetSymbolAddress((void**)&wol, g_wo_l);
    cudaGetSymbolAddress((void**)&w1h, g_w1_h); cudaGetSymbolAddress((void**)&w1l, g_w1_l);
    cudaGetSymbolAddress((void**)&w2h, g_w2_h); cudaGetSymbolAddress((void**)&w2l, g_w2_l);

    cudaFuncSetAttribute(att_out_kernel,
                         cudaFuncAttributeMaxDynamicSharedMemorySize, SM3_BYTES);
    cudaFuncSetAttribute(gemm_mma<0,0>,
                         cudaFuncAttributeMaxDynamicSharedMemorySize, GM_SMEM_BYTES);
    cudaFuncSetAttribute(gemm_mma<1,1>,
                         cudaFuncAttributeMaxDynamicSharedMemorySize, GM_SMEM_BYTES);

    len_kernel<<<BB, 256>>>(x);
    embed_kernel<<<(MM * (DD/4) + 255) / 256, 256>>>(x, emb, pe);

    // batched weight transpose+split: 24 matrices, one launch
    {
        WtcArgs wa = {};
        int idx = 0;
        for (int l = 0; l < NLL; l++) {
            size_t wo = (size_t)l * DD * DD;
            size_t wf = (size_t)l * DD * FF;
            wa.src[idx] = Wq + wo; wa.oh[idx] = wqh + wo; wa.ol[idx] = wql + wo; wa.K[idx] = DD; wa.N[idx] = DD; idx++;
            wa.src[idx] = Wk + wo; wa.oh[idx] = wkh + wo; wa.ol[idx] = wkl + wo; wa.K[idx] = DD; wa.N[idx] = DD; idx++;
            wa.src[idx] = Wv + wo; wa.oh[idx] = wvh + wo; wa.ol[idx] = wvl + wo; wa.K[idx] = DD; wa.N[idx] = DD; idx++;
            wa.src[idx] = Wo + wo; wa.oh[idx] = woh + wo; wa.ol[idx] = wol + wo; wa.K[idx] = DD; wa.N[idx] = DD; idx++;
            wa.src[idx] = W1 + wf; wa.oh[idx] = w1h + wf; wa.ol[idx] = w1l + wf; wa.K[idx] = DD; wa.N[idx] = FF; idx++;
            wa.src[idx] = W2 + wf; wa.oh[idx] = w2h + wf; wa.ol[idx] = w2l + wf; wa.K[idx] = FF; wa.N[idx] = DD; idx++;
        }
        wtc_all_kernel<<<dim3(FF/32, FF/32, 24), dim3(32, 8)>>>(wa);
    }

    for (int l = 0; l < NLL; l++) {
        size_t wo   = (size_t)l * DD * DD;
        size_t wf   = (size_t)l * DD * FF;
        size_t boff = (size_t)l * DD;

        // QKV fused; epilogue applies phi (q), masked phi (k)
        GTArgs ga = {};
        ga.Af = hf; ga.N = DD; ga.K = DD;
        ga.Bh[0] = wqh + wo; ga.Bl[0] = wql + wo;
        ga.Bh[1] = wkh + wo; ga.Bl[1] = wkl + wo;
        ga.Bh[2] = wvh + wo; ga.Bl[2] = wvl + wo;
        ga.bias[0] = bq + boff; ga.bias[1] = bk + boff; ga.bias[2] = bv + boff;
        ga.outf[0] = q; ga.outf[1] = kk; ga.outf[2] = vv;
        ga.pmode[0] = 1; ga.pmode[1] = 2; ga.pmode[2] = 0;
        gemm_mma<0,0><<<dim3(DD/128, MM/128, 3), 256, GM_SMEM_BYTES>>>(ga);

        att_sums_kernel<<<dim3(NCC, BHH), 256>>>();
        att_scan_kernel<<<dim3(BHH, 8), 256>>>();
        att_out_kernel<<<dim3(NCC, BHH), 256, SM3_BYTES>>>();

        // O proj
        GTArgs go = {};
        go.Af = af; go.N = DD; go.K = DD;
        go.Bh[0] = woh + wo; go.Bl[0] = wol + wo;
        go.bias[0] = bo + boff; go.outf[0] = q;
        gemm_mma<0,0><<<dim3(DD/128, MM/128, 1), 256, GM_SMEM_BYTES>>>(go);

        ln_kernel<<<MM, 128>>>(h, q, g1 + boff, be1 + boff, h, hf);

        // FFN1 (relu, fp16 output)
        GTArgs g1a = {};
        g1a.Af = hf; g1a.N = FF; g1a.K = DD;
        g1a.Bh[0] = w1h + wf; g1a.Bl[0] = w1l + wf;
        g1a.bias[0] = b1 + (size_t)l * FF;
        g1a.outh[0] = tf;
        gemm_mma<1,1><<<dim3(FF/128, MM/128, 1), 256, GM_SMEM_BYTES>>>(g1a);

        // FFN2
        GTArgs g2a = {};
        g2a.Af = tf; g2a.N = DD; g2a.K = FF;
        g2a.Bh[0] = w2h + wf; g2a.Bl[0] = w2l + wf;
        g2a.bias[0] = b2 + boff; g2a.outf[0] = q;
        gemm_mma<0,0><<<dim3(DD/128, MM/128, 1), 256, GM_SMEM_BYTES>>>(g2a);

        ln_kernel<<<MM, 128>>>(h, q, g2 + boff, be2 + boff, h, hf);
    }

    ln_kernel<<<MM, 128>>>(h, nullptr, gf, bf, (float*)d_out, nullptr);
}

// round 14
// speedup vs baseline: 1.1473x; 1.0062x over previous
#include <cuda_runtime.h>
#include <cuda_fp16.h>
#include <cstdint>

// ---------------- problem constants ----------------
#define BB  4
#define SS  2048
#define DD  512
#define HH  8
#define DHH 64
#define FF  2048
#define NLL 4
#define MM  (BB*SS)      // 8192 rows
#define CC  64           // attention chunk length
#define NCC (SS/CC)      // 32 chunks
#define BHH (BB*HH)      // 32 (b,h) pairs

__device__ __forceinline__ uint32_t smem_u32(const void* p) {
    uint32_t a;
    asm("{ .reg .u64 t; cvta.to.shared.u64 t, %1; cvt.u32.u64 %0, t; }" : "=r"(a) : "l"(p));
    return a;
}

// ---------------- scratch (device globals; no allocs allowed) ----------------
__device__ float g_h[MM*DD];
__device__ float g_x1[MM*DD];         // fp32 gemm out for LN residual
__device__ float g_S[(size_t)BHH*NCC*DHH*DHH];
__device__ float g_ks[BHH*NCC*DHH];
__device__ int   g_len[BB];

// fp16 activations
__device__ __align__(16) __half g_hf[MM*DD];             // residual stream as GEMM-A
__device__ __align__(16) __half g_qh[MM*DD];             // phi(q)
__device__ __align__(16) __half g_kh[MM*DD];             // masked phi(k)
__device__ __align__(16) __half g_vh[MM*DD];             // v
__device__ __align__(16) __half g_af[MM*DD];             // attention output
__device__ __align__(16) __half g_tf[(size_t)MM*FF];     // FFN hidden

// transposed weights as fp16 hi/lo pairs: layout [N][K]
__device__ __align__(16) __half g_wq_h[NLL*DD*DD], g_wq_l[NLL*DD*DD];
__device__ __align__(16) __half g_wk_h[NLL*DD*DD], g_wk_l[NLL*DD*DD];
__device__ __align__(16) __half g_wv_h[NLL*DD*DD], g_wv_l[NLL*DD*DD];
__device__ __align__(16) __half g_wo_h[NLL*DD*DD], g_wo_l[NLL*DD*DD];
__device__ __align__(16) __half g_w1_h[NLL*FF*DD], g_w1_l[NLL*FF*DD];
__device__ __align__(16) __half g_w2_h[NLL*DD*FF], g_w2_l[NLL*DD*FF];

__device__ __forceinline__ float phi_f(float u) { return u > 0.f ? u + 1.f : __expf(u); }

__device__ __forceinline__ void split_h(float x, __half& h, __half& l) {
    h = __float2half_rn(x);
    l = __float2half_rn(x - __half2float(h));
}

// ---------------- lengths ----------------
__global__ void len_kernel(const int* __restrict__ x) {
    __shared__ int red[256];
    int b = blockIdx.x, tid = threadIdx.x;
    int cnt = 0;
    for (int s = tid; s < SS; s += 256) cnt += (x[b*SS + s] != 0);
    red[tid] = cnt; __syncthreads();
    for (int off = 128; off; off >>= 1) {
        if (tid < off) red[tid] += red[tid + off];
        __syncthreads();
    }
    if (tid == 0) g_len[b] = red[0];
}

// ---------------- embedding + positional (+ fp16 round) ----------------
__global__ void embed_kernel(const int* __restrict__ x,
                             const float* __restrict__ emb,
                             const float* __restrict__ pe) {
    int idx = blockIdx.x * 256 + threadIdx.x;
    if (idx >= MM * (DD/4)) return;
    int i  = idx >> 7;
    int d4 = idx & 127;
    int s  = i & (SS - 1);
    int tok = x[i];
    float4 e = ((const float4*)emb)[(size_t)tok * (DD/4) + d4];
    float4 p = ((const float4*)pe)[(size_t)s * (DD/4) + d4];
    float4 o;
    o.x = e.x + p.x; o.y = e.y + p.y; o.z = e.z + p.z; o.w = e.w + p.w;
    ((float4*)g_h)[idx] = o;
    size_t e0 = (size_t)idx * 4;
    g_hf[e0+0] = __float2half_rn(o.x);
    g_hf[e0+1] = __float2half_rn(o.y);
    g_hf[e0+2] = __float2half_rn(o.z);
    g_hf[e0+3] = __float2half_rn(o.w);
}

// ---------------- batched weight transpose + split (24 matrices, one launch) ----
struct WtcArgs {
    const float* src[24];
    __half* oh[24];
    __half* ol[24];
    int K[24], N[24];
};
__global__ void wtc_all_kernel(WtcArgs p) {
    __shared__ float t[32][33];
    int m = blockIdx.z;
    int K = p.K[m], N = p.N[m];
    int n0 = blockIdx.x * 32, k0 = blockIdx.y * 32;
    if (n0 >= N || k0 >= K) return;
    const float* W = p.src[m];
    __half *oh = p.oh[m], *ol = p.ol[m];
    int tx = threadIdx.x, ty = threadIdx.y;   // 32x8
    #pragma unroll
    for (int i = 0; i < 32; i += 8)
        t[ty + i][tx] = W[(size_t)(k0 + ty + i) * N + n0 + tx];
    __syncthreads();
    #pragma unroll
    for (int i = 0; i < 32; i += 8) {
        float v = t[tx][ty + i];
        size_t o = (size_t)(n0 + ty + i) * K + k0 + tx;
        split_h(v, oh[o], ol[o]);
    }
}

// ---------------- 2-term fp16 GEMM via warp mma.sync ----------------
// C[M,N] = A[M,K] * B[N,K]^T + bias ; A single fp16, B as fp16 (hi,lo) pair.
// C = Af*Bh + Af*Bl.  Block 128x128, BK=32, 256 thr, warp tile 64x32.
// 4-stage cp.async pipeline, swizzled 64B-pitch smem, one sync/iter, 2 CTAs/SM.
// pmode: 0=none, 1=phi, 2=masked phi (applied on BOTH output paths).
struct GTArgs {
    const __half *Af;
    const __half *Bh[3], *Bl[3];
    const float* bias[3];
    float* outf[3];
    __half* outh[3];
    int pmode[3];
    int N, K;
};

#define STAGES 4
#define TILE_BYTES 8192                    // 128 rows x 64B (swizzled)
#define STAGE_BYTES (3*TILE_BYTES)         // Af,Bh,Bl = 24576
#define GM_SMEM_BYTES (STAGES*STAGE_BYTES) // 98304

// swizzled in-tile byte offset for (row, 16B-chunk c): row*64 + (c ^ ((row>>1)&3))*16
__device__ __forceinline__ uint32_t swz(int row, int c) {
    return (uint32_t)(row * 64 + ((c ^ ((row >> 1) & 3)) << 4));
}

#define MMA_F16(d, a, b) \
    asm volatile("mma.sync.aligned.m16n8k16.row.col.f32.f16.f16.f32 " \
        "{%0,%1,%2,%3}, {%4,%5,%6,%7}, {%8,%9}, {%0,%1,%2,%3};" \
        : "+f"((d)[0]), "+f"((d)[1]), "+f"((d)[2]), "+f"((d)[3]) \
        : "r"((a)[0]), "r"((a)[1]), "r"((a)[2]), "r"((a)[3]), "r"((b)[0]), "r"((b)[1]))

#define LDMX4(r, addr) \
    asm volatile("ldmatrix.sync.aligned.m8n8.x4.shared.b16 {%0,%1,%2,%3}, [%4];" \
        : "=r"((r)[0]), "=r"((r)[1]), "=r"((r)[2]), "=r"((r)[3]) : "r"(addr))

template<int RELU, int OUTH>
__global__ void __launch_bounds__(256, 2) gemm_mma(GTArgs p) {
    extern __shared__ __half sm[];
    const uint32_t sbase = smem_u32(sm);
    const int z = blockIdx.z;
    const int N = p.N, K = p.K;
    const int tid = threadIdx.x;
    const int m0 = blockIdx.y * 128, n0 = blockIdx.x * 128;

    // ---- loader: each thread owns (row rA, chunk chk); 6 x 16B per stage
    const int rA  = tid >> 2;          // 0..63
    const int chk = tid & 3;           // 16B chunk within 64B row
    const __half* gp[3];
    gp[0] = p.Af    + (size_t)(m0 + rA) * K + chk * 8;
    gp[1] = p.Bh[z] + (size_t)(n0 + rA) * K + chk * 8;
    gp[2] = p.Bl[z] + (size_t)(n0 + rA) * K + chk * 8;
    const uint32_t s0 = swz(rA, chk);  // rows rA and rA+64 share swizzle bits
    const size_t K64 = (size_t)K << 6; // 64 rows of stride K

    const int wid = tid >> 5, lane = tid & 31;
    const int wm = (wid & 1) * 64;
    const int wn = (wid >> 1) * 32;

    // ---- fragment base offsets (swizzled); kh step = XOR 0x20 ----
    const int rowa = wm + (lane & 15);
    const uint32_t aSw = swz(rowa, (lane >> 4) & 1);
    const int rowb = wn + (lane & 7) + ((lane >> 4) << 3);
    const uint32_t bSw = (uint32_t)TILE_BYTES + swz(rowb, (lane >> 3) & 1);

    float acc[4][4][4];
    #pragma unroll
    for (int a = 0; a < 4; a++)
        #pragma unroll
        for (int b = 0; b < 4; b++)
            #pragma unroll
            for (int c = 0; c < 4; c++) acc[a][b][c] = 0.f;

    const int nt = K >> 5;

    auto load_stage = [&](int slot, int k0) {
        uint32_t sb = sbase + (uint32_t)slot * STAGE_BYTES + s0;
        #pragma unroll
        for (int op = 0; op < 3; op++)
            #pragma unroll
            for (int j = 0; j < 2; j++) {
                asm volatile("cp.async.cg.shared.global [%0], [%1], 16;"
                    :: "r"(sb + (uint32_t)(op * TILE_BYTES + j * 4096)),
                       "l"(gp[op] + (j ? K64 : 0) + k0));
            }
        asm volatile("cp.async.commit_group;" ::: "memory");
    };

    // prologue: 3 stages in flight
    load_stage(0, 0);
    load_stage(1, 32);
    load_stage(2, 64);

    int cslot = 0, lslot = 3;
    for (int t = 0; t < nt; t++) {
        asm volatile("cp.async.wait_group 2;" ::: "memory");
        __syncthreads();
        if (t + 3 < nt) load_stage(lslot, (t + 3) * 32);
        else asm volatile("cp.async.commit_group;" ::: "memory");
        if (++lslot == STAGES) lslot = 0;

        const uint32_t stg = sbase + (uint32_t)cslot * STAGE_BYTES;
        if (++cslot == STAGES) cslot = 0;
        #pragma unroll
        for (int kh = 0; kh < 2; kh++) {
            const uint32_t kx = (uint32_t)(kh * 0x20);   // chunk+2 under swizzle
            // B fragments first (4 loads: Bh,Bl x 2 ng), then A (4 loads).
            uint32_t bfr[2][2][4];
            #pragma unroll
            for (int ng = 0; ng < 2; ng++)
                #pragma unroll
                for (int sp = 0; sp < 2; sp++)
                    LDMX4(bfr[sp][ng],
                          stg + ((bSw + (uint32_t)(sp * TILE_BYTES + ng * 1024)) ^ kx));
            uint32_t afr[4][4];
            #pragma unroll
            for (int mt = 0; mt < 4; mt++)
                LDMX4(afr[mt],
                      stg + ((aSw + (uint32_t)(mt * 1024)) ^ kx));
            // term-major: all Af*Bh, then all Af*Bl (per-acc order preserved).
            #pragma unroll
            for (int mt = 0; mt < 4; mt++)
                #pragma unroll
                for (int nn = 0; nn < 4; nn++) {
                    int ng = nn >> 1, hb = (nn & 1) * 2;
                    uint32_t b0h[2] = { bfr[0][ng][hb], bfr[0][ng][hb+1] };
                    MMA_F16(acc[mt][nn], afr[mt], b0h);  // Af*Bh
                }
            #pragma unroll
            for (int mt = 0; mt < 4; mt++)
                #pragma unroll
                for (int nn = 0; nn < 4; nn++) {
                    int ng = nn >> 1, hb = (nn & 1) * 2;
                    uint32_t b0l[2] = { bfr[1][ng][hb], bfr[1][ng][hb+1] };
                    MMA_F16(acc[mt][nn], afr[mt], b0l);  // Af*Bl
                }
        }
    }

    // ---- epilogue ----
    const float* bias = p.bias[z];
    const int pm = p.pmode[z];
    const int lenb = g_len[m0 >> 11];     // batch fixed per CTA (128 | 2048)
    #pragma unroll
    for (int nn = 0; nn < 4; nn++) {
        int cn = n0 + wn + nn * 8 + (lane & 3) * 2;
        float b0v = bias[cn], b1v = bias[cn + 1];
        #pragma unroll
        for (int mt = 0; mt < 4; mt++) {
            int r0 = m0 + wm + mt * 16 + (lane >> 2);
            #pragma unroll
            for (int half_ = 0; half_ < 2; half_++) {
                int r = r0 + half_ * 8;
                float v0 = acc[mt][nn][half_*2 + 0] + b0v;
                float v1 = acc[mt][nn][half_*2 + 1] + b1v;
                if (RELU) { v0 = fmaxf(v0, 0.f); v1 = fmaxf(v1, 0.f); }
                if (pm == 1) { v0 = phi_f(v0); v1 = phi_f(v1); }
                else if (pm == 2) {
                    if ((r & (SS - 1)) < lenb) { v0 = phi_f(v0); v1 = phi_f(v1); }
                    else { v0 = 0.f; v1 = 0.f; }
                }
                if (OUTH) {
                    __half2 hp;
                    hp.x = __float2half_rn(v0);
                    hp.y = __float2half_rn(v1);
                    *(__half2*)(p.outh[z] + (size_t)r * N + cn) = hp;
                } else {
                    float2 o; o.x = v0; o.y = v1;
                    *(float2*)(p.outf[z] + (size_t)r * N + cn) = o;
                }
            }
        }
    }
}

// ---------------- attention pass 1: per-chunk  S_c = phiK^T V,  ks_c = sum phiK
// g_kh holds masked phi(k) fp16; g_vh raw v fp16.
__global__ void __launch_bounds__(256) att_sums_kernel() {
    __shared__ float sK[CC][68];
    __shared__ float sV[CC][68];
    int c = blockIdx.x, bh = blockIdx.y;
    int b = bh >> 3, h = bh & 7;
    int tid = threadIdx.x;
    #pragma unroll
    for (int it = 0; it < 2; it++) {
        int idx = it * 256 + tid;            // 0..511
        int j  = idx >> 3;                   // row 0..63
        int d8 = (idx & 7) << 3;             // 0..56
        size_t g = ((size_t)(b * SS + c * CC + j)) * DD + h * DHH + d8;
        uint4 kraw = *(const uint4*)&g_kh[g];
        uint4 vraw = *(const uint4*)&g_vh[g];
        const __half2* kp = (const __half2*)&kraw;
        const __half2* vp = (const __half2*)&vraw;
        #pragma unroll
        for (int u = 0; u < 4; u++) {
            float2 kf = __half22float2(kp[u]);
            float2 vf = __half22float2(vp[u]);
            sK[j][d8 + u*2 + 0] = kf.x; sK[j][d8 + u*2 + 1] = kf.y;
            sV[j][d8 + u*2 + 0] = vf.x; sV[j][d8 + u*2 + 1] = vf.y;
        }
    }
    __syncthreads();
    int ti = tid & 15, tj = tid >> 4;
    float acc[4][4];
    #pragma unroll
    for (int r = 0; r < 4; r++)
        #pragma unroll
        for (int e = 0; e < 4; e++) acc[r][e] = 0.f;
    #pragma unroll 8
    for (int j = 0; j < CC; j++) {
        float4 kf = *(const float4*)&sK[j][ti*4];
        float4 vf = *(const float4*)&sV[j][tj*4];
        float ka[4] = {kf.x,kf.y,kf.z,kf.w};
        float va[4] = {vf.x,vf.y,vf.z,vf.w};
        #pragma unroll
        for (int r = 0; r < 4; r++)
            #pragma unroll
            for (int e = 0; e < 4; e++)
                acc[r][e] = fmaf(ka[r], va[e], acc[r][e]);
    }
    float* So = &g_S[((size_t)(bh * NCC + c)) * (DHH * DHH)];
    #pragma unroll
    for (int r = 0; r < 4; r++) {
        int d = ti * 4 + r;
        float4 o; o.x = acc[r][0]; o.y = acc[r][1]; o.z = acc[r][2]; o.w = acc[r][3];
        *(float4*)&So[d * DHH + tj * 4] = o;
    }
    if (tid < DHH) {
        float s = 0.f;
        #pragma unroll 8
        for (int j = 0; j < CC; j++) s += sK[j][tid];
        g_ks[(bh * NCC + c) * DHH + tid] = s;
    }
}

// ---------------- attention pass 2: exclusive prefix over chunks (parallel) -----
__global__ void __launch_bounds__(256) att_scan_kernel() {
    int bh = blockIdx.x, part = blockIdx.y, tid = threadIdx.x;
    int e0 = part * 512 + tid * 2;
    float r0 = 0.f, r1 = 0.f;
    for (int c = 0; c < NCC; c++) {
        float* p = &g_S[((size_t)(bh * NCC + c)) * (DHH*DHH) + e0];
        float2 tv = *(const float2*)p;
        float2 rv; rv.x = r0; rv.y = r1;
        *(float2*)p = rv;
        r0 += tv.x; r1 += tv.y;
    }
    if (part == 0 && tid < DHH) {
        float rk = 0.f;
        for (int c = 0; c < NCC; c++) {
            float* kp = &g_ks[(bh * NCC + c) * DHH + tid];
            float t = *kp; *kp = rk; rk += t;
        }
    }
}

// ---------------- attention pass 3 ----------------
// g_qh holds phi(q) fp16; g_kh masked phi(k) fp16; g_vh v fp16.
#define SM3_FLOATS (3*CC*68 + DHH)
#define SM3_BYTES  (SM3_FLOATS * 4)
__global__ void __launch_bounds__(256) att_out_kernel() {
    extern __shared__ float smf[];
    float* sQ  = smf;
    float* sKV = smf + CC*68;
    float* sSA = smf + 2*CC*68;
    float* skp = smf + 3*CC*68;

    int c = blockIdx.x, bh = blockIdx.y;
    int b = bh >> 3, h = bh & 7;
    int tid = threadIdx.x;

    const float* Sg = &g_S[((size_t)(bh * NCC + c)) * (DHH*DHH)];
    #pragma unroll
    for (int it = 0; it < 2; it++) {
        int idx = it * 256 + tid;            // 0..511
        int r  = idx >> 3;                   // row 0..63
        int d8 = (idx & 7) << 3;             // 0..56
        size_t g = ((size_t)(b * SS + c * CC + r)) * DD + h * DHH + d8;
        uint4 qraw = *(const uint4*)&g_qh[g];
        uint4 kraw = *(const uint4*)&g_kh[g];
        const __half2* qp = (const __half2*)&qraw;
        const __half2* kp = (const __half2*)&kraw;
        #pragma unroll
        for (int u = 0; u < 4; u++) {
            float2 qf = __half22float2(qp[u]);
            float2 kf = __half22float2(kp[u]);
            sQ[(d8+u*2+0)*68 + r] = qf.x;
            sQ[(d8+u*2+1)*68 + r] = qf.y;
            sKV[(d8+u*2+0)*68 + r] = kf.x;
            sKV[(d8+u*2+1)*68 + r] = kf.y;
        }
    }
    #pragma unroll
    for (int it = 0; it < 4; it++) {
        int idx = it * 256 + tid;            // 0..1023
        int r  = idx >> 4;
        int d4 = (idx & 15) << 2;
        float4 s4 = *(const float4*)&Sg[r * DHH + d4];
        *(float4*)&sSA[r*68 + d4] = s4;      // sSA[d][e] with row index = d
    }
    if (tid < DHH) skp[tid] = g_ks[(bh * NCC + c) * DHH + tid];
    __syncthreads();

    int ti = tid & 15, tj = tid >> 4;

    float zi = 0.f;
    if (tid < DHH) {
        #pragma unroll 8
        for (int d = 0; d < DHH; d++) zi += sQ[d*68 + tid] * skp[d];
    }

    float oacc[4][4], aacc[4][4];
    #pragma unroll
    for (int r = 0; r < 4; r++)
        #pragma unroll
        for (int e = 0; e < 4; e++) { oacc[r][e] = 0.f; aacc[r][e] = 0.f; }
    #pragma unroll 4
    for (int d = 0; d < DHH; d++) {
        float4 aq = *(const float4*)&sQ [d*68 + ti*4];
        float4 bs = *(const float4*)&sSA[d*68 + tj*4];
        float4 bk = *(const float4*)&sKV[d*68 + tj*4];
        float qa[4] = {aq.x,aq.y,aq.z,aq.w};
        float sa[4] = {bs.x,bs.y,bs.z,bs.w};
        float ka[4] = {bk.x,bk.y,bk.z,bk.w};
        #pragma unroll
        for (int r = 0; r < 4; r++)
            #pragma unroll
            for (int e = 0; e < 4; e++) {
                oacc[r][e] = fmaf(qa[r], sa[e], oacc[r][e]);
                aacc[r][e] = fmaf(qa[r], ka[e], aacc[r][e]);
            }
    }
    __syncthreads();

    #pragma unroll
    for (int r = 0; r < 4; r++)
        #pragma unroll
        for (int e = 0; e < 4; e++) {
            int i = ti * 4 + r, j = tj * 4 + e;
            sSA[j*68 + i] = (j <= i) ? aacc[r][e] : 0.f;
        }
    #pragma unroll
    for (int it = 0; it < 2; it++) {
        int idx = it * 256 + tid;
        int r  = idx >> 3;
        int e8 = (idx & 7) << 3;
        uint4 vraw = *(const uint4*)&g_vh[((size_t)(b * SS + c * CC + r)) * DD + h * DHH + e8];
        const __half2* vp = (const __half2*)&vraw;
        #pragma unroll
        for (int u = 0; u < 4; u++) {
            float2 vf = __half22float2(vp[u]);
            sKV[r*68 + e8 + u*2 + 0] = vf.x;
            sKV[r*68 + e8 + u*2 + 1] = vf.y;
        }
    }
    __syncthreads();

    if (tid < DHH) {
        float z = zi;
        #pragma unroll 8
        for (int j = 0; j < CC; j++) z += sSA[j*68 + tid];
        skp[tid] = 1.f / (z + 1e-6f);
    }

    #pragma unroll 4
    for (int j = 0; j < CC; j++) {
        float4 aj = *(const float4*)&sSA[j*68 + ti*4];
        float4 ve = *(const float4*)&sKV[j*68 + tj*4];
        float aa[4] = {aj.x,aj.y,aj.z,aj.w};
        float va[4] = {ve.x,ve.y,ve.z,ve.w};
        #pragma unroll
        for (int r = 0; r < 4; r++)
            #pragma unroll
            for (int e = 0; e < 4; e++)
                oacc[r][e] = fmaf(aa[r], va[e], oacc[r][e]);
    }
    __syncthreads();

    #pragma unroll
    for (int r = 0; r < 4; r++) {
        int i = ti * 4 + r;
        float zr = skp[i];
        size_t base = ((size_t)(b * SS + c * CC + i)) * DD + h * DHH + tj * 4;
        #pragma unroll
        for (int e = 0; e < 4; e++) {
            float o = oacc[r][e] * zr;
            g_af[base + e] = __float2half_rn(o);
        }
    }
}

// ---------------- LayerNorm (+ residual, + optional fp16 out) ----------------
__global__ void ln_kernel(const float* __restrict__ x, const float* __restrict__ add,
                          const float* __restrict__ gamma, const float* __restrict__ beta,
                          float* __restrict__ out, __half* __restrict__ oh) {
    __shared__ float rs[4], rq[4];
    int row = blockIdx.x, tid = threadIdx.x;
    float4 v = ((const float4*)(x + (size_t)row * DD))[tid];
    if (add) {
        float4 a = ((const float4*)(add + (size_t)row * DD))[tid];
        v.x += a.x; v.y += a.y; v.z += a.z; v.w += a.w;
    }
    float s = v.x + v.y + v.z + v.w;
    float q = v.x*v.x + v.y*v.y + v.z*v.z + v.w*v.w;
    #pragma unroll
    for (int off = 16; off; off >>= 1) {
        s += __shfl_xor_sync(0xffffffffu, s, off);
        q += __shfl_xor_sync(0xffffffffu, q, off);
    }
    if ((tid & 31) == 0) { rs[tid >> 5] = s; rq[tid >> 5] = q; }
    __syncthreads();
    s = rs[0] + rs[1] + rs[2] + rs[3];
    q = rq[0] + rq[1] + rq[2] + rq[3];
    float mu   = s * (1.f / DD);
    float var  = q * (1.f / DD) - mu * mu;
    float rstd = rsqrtf(var + 1e-5f);
    float4 g  = ((const float4*)gamma)[tid];
    float4 bt = ((const float4*)beta)[tid];
    float4 o;
    o.x = (v.x - mu) * rstd * g.x + bt.x;
    o.y = (v.y - mu) * rstd * g.y + bt.y;
    o.z = (v.z - mu) * rstd * g.z + bt.z;
    o.w = (v.w - mu) * rstd * g.w + bt.w;
    ((float4*)(out + (size_t)row * DD))[tid] = o;
    if (oh) {
        size_t e0 = (size_t)row * DD + tid * 4;
        oh[e0+0] = __float2half_rn(o.x);
        oh[e0+1] = __float2half_rn(o.y);
        oh[e0+2] = __float2half_rn(o.z);
        oh[e0+3] = __float2half_rn(o.w);
    }
}

// ---------------- launch --------------------------------------------------------
extern "C" void kernel_launch(void* const* d_in, const int* in_sizes, int n_in,
                              void* d_out, int out_size) {
    (void)in_sizes; (void)n_in; (void)out_size;
    const int*   x   = (const int*)  d_in[0];
    const float* emb = (const float*)d_in[1];
    const float* pe  = (const float*)d_in[2];
    const float* Wq  = (const float*)d_in[3];
    const float* bq  = (const float*)d_in[4];
    const float* Wk  = (const float*)d_in[5];
    const float* bk  = (const float*)d_in[6];
    const float* Wv  = (const float*)d_in[7];
    const float* bv  = (const float*)d_in[8];
    const float* Wo  = (const float*)d_in[9];
    const float* bo  = (const float*)d_in[10];
    const float* W1  = (const float*)d_in[11];
    const float* b1  = (const float*)d_in[12];
    const float* W2  = (const float*)d_in[13];
    const float* b2  = (const float*)d_in[14];
    const float* g1  = (const float*)d_in[15];
    const float* be1 = (const float*)d_in[16];
    const float* g2  = (const float*)d_in[17];
    const float* be2 = (const float*)d_in[18];
    const float* gf  = (const float*)d_in[19];
    const float* bf  = (const float*)d_in[20];

    float *h, *x1;
    cudaGetSymbolAddress((void**)&h, g_h);
    cudaGetSymbolAddress((void**)&x1, g_x1);
    __half *hf, *qh, *kh2, *vh2, *af, *tf;
    cudaGetSymbolAddress((void**)&hf, g_hf);
    cudaGetSymbolAddress((void**)&qh, g_qh);
    cudaGetSymbolAddress((void**)&kh2, g_kh);
    cudaGetSymbolAddress((void**)&vh2, g_vh);
    cudaGetSymbolAddress((void**)&af, g_af);
    cudaGetSymbolAddress((void**)&tf, g_tf);
    __half *wqh, *wql, *wkh, *wkl, *wvh, *wvl, *woh, *wol, *w1h, *w1l, *w2h, *w2l;
    cudaGetSymbolAddress((void**)&wqh, g_wq_h); cudaGetSymbolAddress((void**)&wql, g_wq_l);
    cudaGetSymbolAddress((void**)&wkh, g_wk_h); cudaGetSymbolAddress((void**)&wkl, g_wk_l);
    cudaGetSymbolAddress((void**)&wvh, g_wv_h); cudaGetSymbolAddress((void**)&wvl, g_wv_l);
    cudaGetSymbolAddress((void**)&woh, g_wo_h); cudaGetSymbolAddress((void**)&wol, g_wo_l);
    cudaGetSymbolAddress((void**)&w1h, g_w1_h); cudaGetSymbolAddress((void**)&w1l, g_w1_l);
    cudaGetSymbolAddress((void**)&w2h, g_w2_h); cudaGetSymbolAddress((void**)&w2l, g_w2_l);

    cudaFuncSetAttribute(att_out_kernel,
                         cudaFuncAttributeMaxDynamicSharedMemorySize, SM3_BYTES);
    cudaFuncSetAttribute(gemm_mma<0,0>,
                         cudaFuncAttributeMaxDynamicSharedMemorySize, GM_SMEM_BYTES);
    cudaFuncSetAttribute(gemm_mma<0,1>,
                         cudaFuncAttributeMaxDynamicSharedMemorySize, GM_SMEM_BYTES);
    cudaFuncSetAttribute(gemm_mma<1,1>,
                         cudaFuncAttributeMaxDynamicSharedMemorySize, GM_SMEM_BYTES);

    len_kernel<<<BB, 256>>>(x);
    embed_kernel<<<(MM * (DD/4) + 255) / 256, 256>>>(x, emb, pe);

    // batched weight transpose+split: 24 matrices, one launch
    {
        WtcArgs wa = {};
        int idx = 0;
        for (int l = 0; l < NLL; l++) {
            size_t wo = (size_t)l * DD * DD;
            size_t wf = (size_t)l * DD * FF;
            wa.src[idx] = Wq + wo; wa.oh[idx] = wqh + wo; wa.ol[idx] = wql + wo; wa.K[idx] = DD; wa.N[idx] = DD; idx++;
            wa.src[idx] = Wk + wo; wa.oh[idx] = wkh + wo; wa.ol[idx] = wkl + wo; wa.K[idx] = DD; wa.N[idx] = DD; idx++;
            wa.src[idx] = Wv + wo; wa.oh[idx] = wvh + wo; wa.ol[idx] = wvl + wo; wa.K[idx] = DD; wa.N[idx] = DD; idx++;
            wa.src[idx] = Wo + wo; wa.oh[idx] = woh + wo; wa.ol[idx] = wol + wo; wa.K[idx] = DD; wa.N[idx] = DD; idx++;
            wa.src[idx] = W1 + wf; wa.oh[idx] = w1h + wf; wa.ol[idx] = w1l + wf; wa.K[idx] = DD; wa.N[idx] = FF; idx++;
            wa.src[idx] = W2 + wf; wa.oh[idx] = w2h + wf; wa.ol[idx] = w2l + wf; wa.K[idx] = FF; wa.N[idx] = DD; idx++;
        }
        wtc_all_kernel<<<dim3(FF/32, FF/32, 24), dim3(32, 8)>>>(wa);
    }

    for (int l = 0; l < NLL; l++) {
        size_t wo   = (size_t)l * DD * DD;
        size_t wf   = (size_t)l * DD * FF;
        size_t boff = (size_t)l * DD;

        // QKV fused; epilogue applies phi (q), masked phi (k); fp16 outputs
        GTArgs ga = {};
        ga.Af = hf; ga.N = DD; ga.K = DD;
        ga.Bh[0] = wqh + wo; ga.Bl[0] = wql + wo;
        ga.Bh[1] = wkh + wo; ga.Bl[1] = wkl + wo;
        ga.Bh[2] = wvh + wo; ga.Bl[2] = wvl + wo;
        ga.bias[0] = bq + boff; ga.bias[1] = bk + boff; ga.bias[2] = bv + boff;
        ga.outh[0] = qh; ga.outh[1] = kh2; ga.outh[2] = vh2;
        ga.pmode[0] = 1; ga.pmode[1] = 2; ga.pmode[2] = 0;
        gemm_mma<0,1><<<dim3(DD/128, MM/128, 3), 256, GM_SMEM_BYTES>>>(ga);

        att_sums_kernel<<<dim3(NCC, BHH), 256>>>();
        att_scan_kernel<<<dim3(BHH, 8), 256>>>();
        att_out_kernel<<<dim3(NCC, BHH), 256, SM3_BYTES>>>();

        // O proj (fp32 out for LN residual)
        GTArgs go = {};
        go.Af = af; go.N = DD; go.K = DD;
        go.Bh[0] = woh + wo; go.Bl[0] = wol + wo;
        go.bias[0] = bo + boff; go.outf[0] = x1;
        gemm_mma<0,0><<<dim3(DD/128, MM/128, 1), 256, GM_SMEM_BYTES>>>(go);

        ln_kernel<<<MM, 128>>>(h, x1, g1 + boff, be1 + boff, h, hf);

        // FFN1 (relu, fp16 output)
        GTArgs g1a = {};
        g1a.Af = hf; g1a.N = FF; g1a.K = DD;
        g1a.Bh[0] = w1h + wf; g1a.Bl[0] = w1l + wf;
        g1a.bias[0] = b1 + (size_t)l * FF;
        g1a.outh[0] = tf;
        gemm_mma<1,1><<<dim3(FF/128, MM/128, 1), 256, GM_SMEM_BYTES>>>(g1a);

        // FFN2 (fp32 out for LN residual)
        GTArgs g2a = {};
        g2a.Af = tf; g2a.N = DD; g2a.K = FF;
        g2a.Bh[0] = w2h + wf; g2a.Bl[0] = w2l + wf;
        g2a.bias[0] = b2 + boff; g2a.outf[0] = x1;
        gemm_mma<0,0><<<dim3(DD/128, MM/128, 1), 256, GM_SMEM_BYTES>>>(g2a);

        ln_kernel<<<MM, 128>>>(h, x1, g2 + boff, be2 + boff, h, hf);
    }

    ln_kernel<<<MM, 128>>>(h, nullptr, gf, bf, (float*)d_out, nullptr);
}

// round 15
// speedup vs baseline: 1.5373x; 1.3399x over previous
#include <cuda_runtime.h>
#include <cuda_fp16.h>
#include <cstdint>

// ---------------- problem constants ----------------
#define BB  4
#define SS  2048
#define DD  512
#define HH  8
#define DHH 64
#define FF  2048
#define NLL 4
#define MM  (BB*SS)      // 8192 rows
#define CC  64           // attention chunk length
#define NCC (SS/CC)      // 32 chunks
#define BHH (BB*HH)      // 32 (b,h) pairs

__device__ __forceinline__ uint32_t smem_u32(const void* p) {
    uint32_t a;
    asm("{ .reg .u64 t; cvta.to.shared.u64 t, %1; cvt.u32.u64 %0, t; }" : "=r"(a) : "l"(p));
    return a;
}

// ---------------- scratch (device globals; no allocs allowed) ----------------
__device__ float g_h[MM*DD];
__device__ float g_x1[MM*DD];         // fp32 gemm out for LN residual
__device__ float g_S[(size_t)BHH*NCC*DHH*DHH];
__device__ float g_ks[BHH*NCC*DHH];
__device__ int   g_len[BB];

// fp16 activations
__device__ __align__(16) __half g_hf[MM*DD];             // residual stream as GEMM-A
__device__ __align__(16) __half g_qh[MM*DD];             // phi(q)
__device__ __align__(16) __half g_kh[MM*DD];             // masked phi(k)
__device__ __align__(16) __half g_vh[MM*DD];             // v
__device__ __align__(16) __half g_af[MM*DD];             // attention output
__device__ __align__(16) __half g_tf[(size_t)MM*FF];     // FFN hidden

// transposed weights fp16 (single-rounded): layout [N][K]
__device__ __align__(16) __half g_wq[NLL*DD*DD];
__device__ __align__(16) __half g_wk[NLL*DD*DD];
__device__ __align__(16) __half g_wv[NLL*DD*DD];
__device__ __align__(16) __half g_wo[NLL*DD*DD];
__device__ __align__(16) __half g_w1[NLL*FF*DD];
__device__ __align__(16) __half g_w2[NLL*DD*FF];

__device__ __forceinline__ float phi_f(float u) { return u > 0.f ? u + 1.f : __expf(u); }

// ---------------- lengths ----------------
__global__ void len_kernel(const int* __restrict__ x) {
    __shared__ int red[256];
    int b = blockIdx.x, tid = threadIdx.x;
    int cnt = 0;
    for (int s = tid; s < SS; s += 256) cnt += (x[b*SS + s] != 0);
    red[tid] = cnt; __syncthreads();
    for (int off = 128; off; off >>= 1) {
        if (tid < off) red[tid] += red[tid + off];
        __syncthreads();
    }
    if (tid == 0) g_len[b] = red[0];
}

// ---------------- embedding + positional (+ fp16 round) ----------------
__global__ void embed_kernel(const int* __restrict__ x,
                             const float* __restrict__ emb,
                             const float* __restrict__ pe) {
    int idx = blockIdx.x * 256 + threadIdx.x;
    if (idx >= MM * (DD/4)) return;
    int i  = idx >> 7;
    int d4 = idx & 127;
    int s  = i & (SS - 1);
    int tok = x[i];
    float4 e = ((const float4*)emb)[(size_t)tok * (DD/4) + d4];
    float4 p = ((const float4*)pe)[(size_t)s * (DD/4) + d4];
    float4 o;
    o.x = e.x + p.x; o.y = e.y + p.y; o.z = e.z + p.z; o.w = e.w + p.w;
    ((float4*)g_h)[idx] = o;
    size_t e0 = (size_t)idx * 4;
    g_hf[e0+0] = __float2half_rn(o.x);
    g_hf[e0+1] = __float2half_rn(o.y);
    g_hf[e0+2] = __float2half_rn(o.z);
    g_hf[e0+3] = __float2half_rn(o.w);
}

// ---------------- batched weight transpose + fp16 round (24 matrices) ----------
struct WtcArgs {
    const float* src[24];
    __half* oh[24];
    int K[24], N[24];
};
__global__ void wtc_all_kernel(WtcArgs p) {
    __shared__ float t[32][33];
    int m = blockIdx.z;
    int K = p.K[m], N = p.N[m];
    int n0 = blockIdx.x * 32, k0 = blockIdx.y * 32;
    if (n0 >= N || k0 >= K) return;
    const float* W = p.src[m];
    __half *oh = p.oh[m];
    int tx = threadIdx.x, ty = threadIdx.y;   // 32x8
    #pragma unroll
    for (int i = 0; i < 32; i += 8)
        t[ty + i][tx] = W[(size_t)(k0 + ty + i) * N + n0 + tx];
    __syncthreads();
    #pragma unroll
    for (int i = 0; i < 32; i += 8) {
        float v = t[tx][ty + i];
        oh[(size_t)(n0 + ty + i) * K + k0 + tx] = __float2half_rn(v);
    }
}

// ---------------- single-term fp16 GEMM via warp mma.sync ----------------
// C[M,N] = A[M,K] * B[N,K]^T + bias ; A,B single-rounded fp16, fp32 accum.
// Block 128x128, BK=32, 256 thr, warp tile 64x32.
// 4-stage cp.async pipeline, swizzled 64B-pitch smem, one sync/iter, 2 CTAs/SM.
// pmode: 0=none, 1=phi, 2=masked phi (applied on BOTH output paths).
struct GTArgs {
    const __half *Af;
    const __half *Bf[3];
    const float* bias[3];
    float* outf[3];
    __half* outh[3];
    int pmode[3];
    int N, K;
};

#define STAGES 4
#define TILE_BYTES 8192                    // 128 rows x 64B (swizzled)
#define STAGE_BYTES (2*TILE_BYTES)         // Af,Bf = 16384
#define GM_SMEM_BYTES (STAGES*STAGE_BYTES) // 65536

// swizzled in-tile byte offset for (row, 16B-chunk c): row*64 + (c ^ ((row>>1)&3))*16
__device__ __forceinline__ uint32_t swz(int row, int c) {
    return (uint32_t)(row * 64 + ((c ^ ((row >> 1) & 3)) << 4));
}

#define MMA_F16(d, a, b) \
    asm volatile("mma.sync.aligned.m16n8k16.row.col.f32.f16.f16.f32 " \
        "{%0,%1,%2,%3}, {%4,%5,%6,%7}, {%8,%9}, {%0,%1,%2,%3};" \
        : "+f"((d)[0]), "+f"((d)[1]), "+f"((d)[2]), "+f"((d)[3]) \
        : "r"((a)[0]), "r"((a)[1]), "r"((a)[2]), "r"((a)[3]), "r"((b)[0]), "r"((b)[1]))

#define LDMX4(r, addr) \
    asm volatile("ldmatrix.sync.aligned.m8n8.x4.shared.b16 {%0,%1,%2,%3}, [%4];" \
        : "=r"((r)[0]), "=r"((r)[1]), "=r"((r)[2]), "=r"((r)[3]) : "r"(addr))

template<int RELU, int OUTH>
__global__ void __launch_bounds__(256, 2) gemm_mma(GTArgs p) {
    extern __shared__ __half sm[];
    const uint32_t sbase = smem_u32(sm);
    const int z = blockIdx.z;
    const int N = p.N, K = p.K;
    const int tid = threadIdx.x;
    const int m0 = blockIdx.y * 128, n0 = blockIdx.x * 128;

    // ---- loader: each thread owns (row rA, chunk chk); 4 x 16B per stage
    const int rA  = tid >> 2;          // 0..63
    const int chk = tid & 3;           // 16B chunk within 64B row
    const __half* gp[2];
    gp[0] = p.Af    + (size_t)(m0 + rA) * K + chk * 8;
    gp[1] = p.Bf[z] + (size_t)(n0 + rA) * K + chk * 8;
    const uint32_t s0 = swz(rA, chk);  // rows rA and rA+64 share swizzle bits
    const size_t K64 = (size_t)K << 6; // 64 rows of stride K

    const int wid = tid >> 5, lane = tid & 31;
    const int wm = (wid & 1) * 64;
    const int wn = (wid >> 1) * 32;

    // ---- fragment base offsets (swizzled); kh step = XOR 0x20 ----
    const int rowa = wm + (lane & 15);
    const uint32_t aSw = swz(rowa, (lane >> 4) & 1);
    const int rowb = wn + (lane & 7) + ((lane >> 4) << 3);
    const uint32_t bSw = (uint32_t)TILE_BYTES + swz(rowb, (lane >> 3) & 1);

    float acc[4][4][4];
    #pragma unroll
    for (int a = 0; a < 4; a++)
        #pragma unroll
        for (int b = 0; b < 4; b++)
            #pragma unroll
            for (int c = 0; c < 4; c++) acc[a][b][c] = 0.f;

    const int nt = K >> 5;

    auto load_stage = [&](int slot, int k0) {
        uint32_t sb = sbase + (uint32_t)slot * STAGE_BYTES + s0;
        #pragma unroll
        for (int op = 0; op < 2; op++)
            #pragma unroll
            for (int j = 0; j < 2; j++) {
                asm volatile("cp.async.cg.shared.global [%0], [%1], 16;"
                    :: "r"(sb + (uint32_t)(op * TILE_BYTES + j * 4096)),
                       "l"(gp[op] + (j ? K64 : 0) + k0));
            }
        asm volatile("cp.async.commit_group;" ::: "memory");
    };

    // prologue: 3 stages in flight
    load_stage(0, 0);
    load_stage(1, 32);
    load_stage(2, 64);

    int cslot = 0, lslot = 3;
    for (int t = 0; t < nt; t++) {
        asm volatile("cp.async.wait_group 2;" ::: "memory");
        __syncthreads();
        if (t + 3 < nt) load_stage(lslot, (t + 3) * 32);
        else asm volatile("cp.async.commit_group;" ::: "memory");
        if (++lslot == STAGES) lslot = 0;

        const uint32_t stg = sbase + (uint32_t)cslot * STAGE_BYTES;
        if (++cslot == STAGES) cslot = 0;
        #pragma unroll
        for (int kh = 0; kh < 2; kh++) {
            const uint32_t kx = (uint32_t)(kh * 0x20);   // chunk+2 under swizzle
            // B fragments first (2 loads), then A (4 loads).
            uint32_t bfr[2][4];
            #pragma unroll
            for (int ng = 0; ng < 2; ng++)
                LDMX4(bfr[ng],
                      stg + ((bSw + (uint32_t)(ng * 1024)) ^ kx));
            uint32_t afr[4][4];
            #pragma unroll
            for (int mt = 0; mt < 4; mt++)
                LDMX4(afr[mt],
                      stg + ((aSw + (uint32_t)(mt * 1024)) ^ kx));
            #pragma unroll
            for (int mt = 0; mt < 4; mt++)
                #pragma unroll
                for (int nn = 0; nn < 4; nn++) {
                    int ng = nn >> 1, hb = (nn & 1) * 2;
                    uint32_t b2[2] = { bfr[ng][hb], bfr[ng][hb+1] };
                    MMA_F16(acc[mt][nn], afr[mt], b2);
                }
        }
    }

    // ---- epilogue ----
    const float* bias = p.bias[z];
    const int pm = p.pmode[z];
    const int lenb = g_len[m0 >> 11];     // batch fixed per CTA (128 | 2048)
    #pragma unroll
    for (int nn = 0; nn < 4; nn++) {
        int cn = n0 + wn + nn * 8 + (lane & 3) * 2;
        float b0v = bias[cn], b1v = bias[cn + 1];
        #pragma unroll
        for (int mt = 0; mt < 4; mt++) {
            int r0 = m0 + wm + mt * 16 + (lane >> 2);
            #pragma unroll
            for (int half_ = 0; half_ < 2; half_++) {
                int r = r0 + half_ * 8;
                float v0 = acc[mt][nn][half_*2 + 0] + b0v;
                float v1 = acc[mt][nn][half_*2 + 1] + b1v;
                if (RELU) { v0 = fmaxf(v0, 0.f); v1 = fmaxf(v1, 0.f); }
                if (pm == 1) { v0 = phi_f(v0); v1 = phi_f(v1); }
                else if (pm == 2) {
                    if ((r & (SS - 1)) < lenb) { v0 = phi_f(v0); v1 = phi_f(v1); }
                    else { v0 = 0.f; v1 = 0.f; }
                }
                if (OUTH) {
                    __half2 hp;
                    hp.x = __float2half_rn(v0);
                    hp.y = __float2half_rn(v1);
                    *(__half2*)(p.outh[z] + (size_t)r * N + cn) = hp;
                } else {
                    float2 o; o.x = v0; o.y = v1;
                    *(float2*)(p.outf[z] + (size_t)r * N + cn) = o;
                }
            }
        }
    }
}

// ---------------- attention pass 1: per-chunk  S_c = phiK^T V,  ks_c = sum phiK
// g_kh holds masked phi(k) fp16; g_vh raw v fp16.
__global__ void __launch_bounds__(256) att_sums_kernel() {
    __shared__ float sK[CC][68];
    __shared__ float sV[CC][68];
    int c = blockIdx.x, bh = blockIdx.y;
    int b = bh >> 3, h = bh & 7;
    int tid = threadIdx.x;
    #pragma unroll
    for (int it = 0; it < 2; it++) {
        int idx = it * 256 + tid;            // 0..511
        int j  = idx >> 3;                   // row 0..63
        int d8 = (idx & 7) << 3;             // 0..56
        size_t g = ((size_t)(b * SS + c * CC + j)) * DD + h * DHH + d8;
        uint4 kraw = *(const uint4*)&g_kh[g];
        uint4 vraw = *(const uint4*)&g_vh[g];
        const __half2* kp = (const __half2*)&kraw;
        const __half2* vp = (const __half2*)&vraw;
        #pragma unroll
        for (int u = 0; u < 4; u++) {
            float2 kf = __half22float2(kp[u]);
            float2 vf = __half22float2(vp[u]);
            sK[j][d8 + u*2 + 0] = kf.x; sK[j][d8 + u*2 + 1] = kf.y;
            sV[j][d8 + u*2 + 0] = vf.x; sV[j][d8 + u*2 + 1] = vf.y;
        }
    }
    __syncthreads();
    int ti = tid & 15, tj = tid >> 4;
    float acc[4][4];
    #pragma unroll
    for (int r = 0; r < 4; r++)
        #pragma unroll
        for (int e = 0; e < 4; e++) acc[r][e] = 0.f;
    #pragma unroll 8
    for (int j = 0; j < CC; j++) {
        float4 kf = *(const float4*)&sK[j][ti*4];
        float4 vf = *(const float4*)&sV[j][tj*4];
        float ka[4] = {kf.x,kf.y,kf.z,kf.w};
        float va[4] = {vf.x,vf.y,vf.z,vf.w};
        #pragma unroll
        for (int r = 0; r < 4; r++)
            #pragma unroll
            for (int e = 0; e < 4; e++)
                acc[r][e] = fmaf(ka[r], va[e], acc[r][e]);
    }
    float* So = &g_S[((size_t)(bh * NCC + c)) * (DHH * DHH)];
    #pragma unroll
    for (int r = 0; r < 4; r++) {
        int d = ti * 4 + r;
        float4 o; o.x = acc[r][0]; o.y = acc[r][1]; o.z = acc[r][2]; o.w = acc[r][3];
        *(float4*)&So[d * DHH + tj * 4] = o;
    }
    if (tid < DHH) {
        float s = 0.f;
        #pragma unroll 8
        for (int j = 0; j < CC; j++) s += sK[j][tid];
        g_ks[(bh * NCC + c) * DHH + tid] = s;
    }
}

// ---------------- attention pass 2: exclusive prefix over chunks (parallel) -----
__global__ void __launch_bounds__(256) att_scan_kernel() {
    int bh = blockIdx.x, part = blockIdx.y, tid = threadIdx.x;
    int e0 = part * 512 + tid * 2;
    float r0 = 0.f, r1 = 0.f;
    for (int c = 0; c < NCC; c++) {
        float* p = &g_S[((size_t)(bh * NCC + c)) * (DHH*DHH) + e0];
        float2 tv = *(const float2*)p;
        float2 rv; rv.x = r0; rv.y = r1;
        *(float2*)p = rv;
        r0 += tv.x; r1 += tv.y;
    }
    if (part == 0 && tid < DHH) {
        float rk = 0.f;
        for (int c = 0; c < NCC; c++) {
            float* kp = &g_ks[(bh * NCC + c) * DHH + tid];
            float t = *kp; *kp = rk; rk += t;
        }
    }
}

// ---------------- attention pass 3 ----------------
// g_qh holds phi(q) fp16; g_kh masked phi(k) fp16; g_vh v fp16.
#define SM3_FLOATS (3*CC*68 + DHH)
#define SM3_BYTES  (SM3_FLOATS * 4)
__global__ void __launch_bounds__(256) att_out_kernel() {
    extern __shared__ float smf[];
    float* sQ  = smf;
    float* sKV = smf + CC*68;
    float* sSA = smf + 2*CC*68;
    float* skp = smf + 3*CC*68;

    int c = blockIdx.x, bh = blockIdx.y;
    int b = bh >> 3, h = bh & 7;
    int tid = threadIdx.x;

    const float* Sg = &g_S[((size_t)(bh * NCC + c)) * (DHH*DHH)];
    #pragma unroll
    for (int it = 0; it < 2; it++) {
        int idx = it * 256 + tid;            // 0..511
        int r  = idx >> 3;                   // row 0..63
        int d8 = (idx & 7) << 3;             // 0..56
        size_t g = ((size_t)(b * SS + c * CC + r)) * DD + h * DHH + d8;
        uint4 qraw = *(const uint4*)&g_qh[g];
        uint4 kraw = *(const uint4*)&g_kh[g];
        const __half2* qp = (const __half2*)&qraw;
        const __half2* kp = (const __half2*)&kraw;
        #pragma unroll
        for (int u = 0; u < 4; u++) {
            float2 qf = __half22float2(qp[u]);
            float2 kf = __half22float2(kp[u]);
            sQ[(d8+u*2+0)*68 + r] = qf.x;
            sQ[(d8+u*2+1)*68 + r] = qf.y;
            sKV[(d8+u*2+0)*68 + r] = kf.x;
            sKV[(d8+u*2+1)*68 + r] = kf.y;
        }
    }
    #pragma unroll
    for (int it = 0; it < 4; it++) {
        int idx = it * 256 + tid;            // 0..1023
        int r  = idx >> 4;
        int d4 = (idx & 15) << 2;
        float4 s4 = *(const float4*)&Sg[r * DHH + d4];
        *(float4*)&sSA[r*68 + d4] = s4;      // sSA[d][e] with row index = d
    }
    if (tid < DHH) skp[tid] = g_ks[(bh * NCC + c) * DHH + tid];
    __syncthreads();

    int ti = tid & 15, tj = tid >> 4;

    float zi = 0.f;
    if (tid < DHH) {
        #pragma unroll 8
        for (int d = 0; d < DHH; d++) zi += sQ[d*68 + tid] * skp[d];
    }

    float oacc[4][4], aacc[4][4];
    #pragma unroll
    for (int r = 0; r < 4; r++)
        #pragma unroll
        for (int e = 0; e < 4; e++) { oacc[r][e] = 0.f; aacc[r][e] = 0.f; }
    #pragma unroll 4
    for (int d = 0; d < DHH; d++) {
        float4 aq = *(const float4*)&sQ [d*68 + ti*4];
        float4 bs = *(const float4*)&sSA[d*68 + tj*4];
        float4 bk = *(const float4*)&sKV[d*68 + tj*4];
        float qa[4] = {aq.x,aq.y,aq.z,aq.w};
        float sa[4] = {bs.x,bs.y,bs.z,bs.w};
        float ka[4] = {bk.x,bk.y,bk.z,bk.w};
        #pragma unroll
        for (int r = 0; r < 4; r++)
            #pragma unroll
            for (int e = 0; e < 4; e++) {
                oacc[r][e] = fmaf(qa[r], sa[e], oacc[r][e]);
                aacc[r][e] = fmaf(qa[r], ka[e], aacc[r][e]);
            }
    }
    __syncthreads();

    #pragma unroll
    for (int r = 0; r < 4; r++)
        #pragma unroll
        for (int e = 0; e < 4; e++) {
            int i = ti * 4 + r, j = tj * 4 + e;
            sSA[j*68 + i] = (j <= i) ? aacc[r][e] : 0.f;
        }
    #pragma unroll
    for (int it = 0; it < 2; it++) {
        int idx = it * 256 + tid;
        int r  = idx >> 3;
        int e8 = (idx & 7) << 3;
        uint4 vraw = *(const uint4*)&g_vh[((size_t)(b * SS + c * CC + r)) * DD + h * DHH + e8];
        const __half2* vp = (const __half2*)&vraw;
        #pragma unroll
        for (int u = 0; u < 4; u++) {
            float2 vf = __half22float2(vp[u]);
            sKV[r*68 + e8 + u*2 + 0] = vf.x;
            sKV[r*68 + e8 + u*2 + 1] = vf.y;
        }
    }
    __syncthreads();

    if (tid < DHH) {
        float z = zi;
        #pragma unroll 8
        for (int j = 0; j < CC; j++) z += sSA[j*68 + tid];
        skp[tid] = 1.f / (z + 1e-6f);
    }

    #pragma unroll 4
    for (int j = 0; j < CC; j++) {
        float4 aj = *(const float4*)&sSA[j*68 + ti*4];
        float4 ve = *(const float4*)&sKV[j*68 + tj*4];
        float aa[4] = {aj.x,aj.y,aj.z,aj.w};
        float va[4] = {ve.x,ve.y,ve.z,ve.w};
        #pragma unroll
        for (int r = 0; r < 4; r++)
            #pragma unroll
            for (int e = 0; e < 4; e++)
                oacc[r][e] = fmaf(aa[r], va[e], oacc[r][e]);
    }
    __syncthreads();

    #pragma unroll
    for (int r = 0; r < 4; r++) {
        int i = ti * 4 + r;
        float zr = skp[i];
        size_t base = ((size_t)(b * SS + c * CC + i)) * DD + h * DHH + tj * 4;
        #pragma unroll
        for (int e = 0; e < 4; e++) {
            float o = oacc[r][e] * zr;
            g_af[base + e] = __float2half_rn(o);
        }
    }
}

// ---------------- LayerNorm (+ residual, + optional fp16 out) ----------------
__global__ void ln_kernel(const float* __restrict__ x, const float* __restrict__ add,
                          const float* __restrict__ gamma, const float* __restrict__ beta,
                          float* __restrict__ out, __half* __restrict__ oh) {
    __shared__ float rs[4], rq[4];
    int row = blockIdx.x, tid = threadIdx.x;
    float4 v = ((const float4*)(x + (size_t)row * DD))[tid];
    if (add) {
        float4 a = ((const float4*)(add + (size_t)row * DD))[tid];
        v.x += a.x; v.y += a.y; v.z += a.z; v.w += a.w;
    }
    float s = v.x + v.y + v.z + v.w;
    float q = v.x*v.x + v.y*v.y + v.z*v.z + v.w*v.w;
    #pragma unroll
    for (int off = 16; off; off >>= 1) {
        s += __shfl_xor_sync(0xffffffffu, s, off);
        q += __shfl_xor_sync(0xffffffffu, q, off);
    }
    if ((tid & 31) == 0) { rs[tid >> 5] = s; rq[tid >> 5] = q; }
    __syncthreads();
    s = rs[0] + rs[1] + rs[2] + rs[3];
    q = rq[0] + rq[1] + rq[2] + rq[3];
    float mu   = s * (1.f / DD);
    float var  = q * (1.f / DD) - mu * mu;
    float rstd = rsqrtf(var + 1e-5f);
    float4 g  = ((const float4*)gamma)[tid];
    float4 bt = ((const float4*)beta)[tid];
    float4 o;
    o.x = (v.x - mu) * rstd * g.x + bt.x;
    o.y = (v.y - mu) * rstd * g.y + bt.y;
    o.z = (v.z - mu) * rstd * g.z + bt.z;
    o.w = (v.w - mu) * rstd * g.w + bt.w;
    ((float4*)(out + (size_t)row * DD))[tid] = o;
    if (oh) {
        size_t e0 = (size_t)row * DD + tid * 4;
        oh[e0+0] = __float2half_rn(o.x);
        oh[e0+1] = __float2half_rn(o.y);
        oh[e0+2] = __float2half_rn(o.z);
        oh[e0+3] = __float2half_rn(o.w);
    }
}

// ---------------- launch --------------------------------------------------------
extern "C" void kernel_launch(void* const* d_in, const int* in_sizes, int n_in,
                              void* d_out, int out_size) {
    (void)in_sizes; (void)n_in; (void)out_size;
    const int*   x   = (const int*)  d_in[0];
    const float* emb = (const float*)d_in[1];
    const float* pe  = (const float*)d_in[2];
    const float* Wq  = (const float*)d_in[3];
    const float* bq  = (const float*)d_in[4];
    const float* Wk  = (const float*)d_in[5];
    const float* bk  = (const float*)d_in[6];
    const float* Wv  = (const float*)d_in[7];
    const float* bv  = (const float*)d_in[8];
    const float* Wo  = (const float*)d_in[9];
    const float* bo  = (const float*)d_in[10];
    const float* W1  = (const float*)d_in[11];
    const float* b1  = (const float*)d_in[12];
    const float* W2  = (const float*)d_in[13];
    const float* b2  = (const float*)d_in[14];
    const float* g1  = (const float*)d_in[15];
    const float* be1 = (const float*)d_in[16];
    const float* g2  = (const float*)d_in[17];
    const float* be2 = (const float*)d_in[18];
    const float* gf  = (const float*)d_in[19];
    const float* bf  = (const float*)d_in[20];

    float *h, *x1;
    cudaGetSymbolAddress((void**)&h, g_h);
    cudaGetSymbolAddress((void**)&x1, g_x1);
    __half *hf, *qh, *kh2, *vh2, *af, *tf;
    cudaGetSymbolAddress((void**)&hf, g_hf);
    cudaGetSymbolAddress((void**)&qh, g_qh);
    cudaGetSymbolAddress((void**)&kh2, g_kh);
    cudaGetSymbolAddress((void**)&vh2, g_vh);
    cudaGetSymbolAddress((void**)&af, g_af);
    cudaGetSymbolAddress((void**)&tf, g_tf);
    __half *wq, *wk, *wv, *wo2, *w1, *w2;
    cudaGetSymbolAddress((void**)&wq, g_wq);
    cudaGetSymbolAddress((void**)&wk, g_wk);
    cudaGetSymbolAddress((void**)&wv, g_wv);
    cudaGetSymbolAddress((void**)&wo2, g_wo);
    cudaGetSymbolAddress((void**)&w1, g_w1);
    cudaGetSymbolAddress((void**)&w2, g_w2);

    cudaFuncSetAttribute(att_out_kernel,
                         cudaFuncAttributeMaxDynamicSharedMemorySize, SM3_BYTES);
    cudaFuncSetAttribute(gemm_mma<0,0>,
                         cudaFuncAttributeMaxDynamicSharedMemorySize, GM_SMEM_BYTES);
    cudaFuncSetAttribute(gemm_mma<0,1>,
                         cudaFuncAttributeMaxDynamicSharedMemorySize, GM_SMEM_BYTES);
    cudaFuncSetAttribute(gemm_mma<1,1>,
                         cudaFuncAttributeMaxDynamicSharedMemorySize, GM_SMEM_BYTES);

    len_kernel<<<BB, 256>>>(x);
    embed_kernel<<<(MM * (DD/4) + 255) / 256, 256>>>(x, emb, pe);

    // batched weight transpose+round: 24 matrices, one launch
    {
        WtcArgs wa = {};
        int idx = 0;
        for (int l = 0; l < NLL; l++) {
            size_t wo = (size_t)l * DD * DD;
            size_t wf = (size_t)l * DD * FF;
            wa.src[idx] = Wq + wo; wa.oh[idx] = wq + wo; wa.K[idx] = DD; wa.N[idx] = DD; idx++;
            wa.src[idx] = Wk + wo; wa.oh[idx] = wk + wo; wa.K[idx] = DD; wa.N[idx] = DD; idx++;
            wa.src[idx] = Wv + wo; wa.oh[idx] = wv + wo; wa.K[idx] = DD; wa.N[idx] = DD; idx++;
            wa.src[idx] = Wo + wo; wa.oh[idx] = wo2 + wo; wa.K[idx] = DD; wa.N[idx] = DD; idx++;
            wa.src[idx] = W1 + wf; wa.oh[idx] = w1 + wf; wa.K[idx] = DD; wa.N[idx] = FF; idx++;
            wa.src[idx] = W2 + wf; wa.oh[idx] = w2 + wf; wa.K[idx] = FF; wa.N[idx] = DD; idx++;
        }
        wtc_all_kernel<<<dim3(FF/32, FF/32, 24), dim3(32, 8)>>>(wa);
    }

    for (int l = 0; l < NLL; l++) {
        size_t wo   = (size_t)l * DD * DD;
        size_t wf   = (size_t)l * DD * FF;
        size_t boff = (size_t)l * DD;

        // QKV fused; epilogue applies phi (q), masked phi (k); fp16 outputs
        GTArgs ga = {};
        ga.Af = hf; ga.N = DD; ga.K = DD;
        ga.Bf[0] = wq + wo;
        ga.Bf[1] = wk + wo;
        ga.Bf[2] = wv + wo;
        ga.bias[0] = bq + boff; ga.bias[1] = bk + boff; ga.bias[2] = bv + boff;
        ga.outh[0] = qh; ga.outh[1] = kh2; ga.outh[2] = vh2;
        ga.pmode[0] = 1; ga.pmode[1] = 2; ga.pmode[2] = 0;
        gemm_mma<0,1><<<dim3(DD/128, MM/128, 3), 256, GM_SMEM_BYTES>>>(ga);

        att_sums_kernel<<<dim3(NCC, BHH), 256>>>();
        att_scan_kernel<<<dim3(BHH, 8), 256>>>();
        att_out_kernel<<<dim3(NCC, BHH), 256, SM3_BYTES>>>();

        // O proj (fp32 out for LN residual)
        GTArgs go = {};
        go.Af = af; go.N = DD; go.K = DD;
        go.Bf[0] = wo2 + wo;
        go.bias[0] = bo + boff; go.outf[0] = x1;
        gemm_mma<0,0><<<dim3(DD/128, MM/128, 1), 256, GM_SMEM_BYTES>>>(go);

        ln_kernel<<<MM, 128>>>(h, x1, g1 + boff, be1 + boff, h, hf);

        // FFN1 (relu, fp16 output)
        GTArgs g1a = {};
        g1a.Af = hf; g1a.N = FF; g1a.K = DD;
        g1a.Bf[0] = w1 + wf;
        g1a.bias[0] = b1 + (size_t)l * FF;
        g1a.outh[0] = tf;
        gemm_mma<1,1><<<dim3(FF/128, MM/128, 1), 256, GM_SMEM_BYTES>>>(g1a);

        // FFN2 (fp32 out for LN residual)
        GTArgs g2a = {};
        g2a.Af = tf; g2a.N = DD; g2a.K = FF;
        g2a.Bf[0] = w2 + wf;
        g2a.bias[0] = b2 + boff; g2a.outf[0] = x1;
        gemm_mma<0,0><<<dim3(DD/128, MM/128, 1), 256, GM_SMEM_BYTES>>>(g2a);

        ln_kernel<<<MM, 128>>>(h, x1, g2 + boff, be2 + boff, h, hf);
    }

    ln_kernel<<<MM, 128>>>(h, nullptr, gf, bf, (float*)d_out, nullptr);
}

// round 16
// speedup vs baseline: 1.6148x; 1.0504x over previous
#include <cuda_runtime.h>
#include <cuda_fp16.h>
#include <cstdint>

// ---------------- problem constants ----------------
#define BB  4
#define SS  2048
#define DD  512
#define HH  8
#define DHH 64
#define FF  2048
#define NLL 4
#define MM  (BB*SS)      // 8192 rows
#define CC  64           // attention chunk length
#define NCC (SS/CC)      // 32 chunks
#define BHH (BB*HH)      // 32 (b,h) pairs

__device__ __forceinline__ uint32_t smem_u32(const void* p) {
    uint32_t a;
    asm("{ .reg .u64 t; cvta.to.shared.u64 t, %1; cvt.u32.u64 %0, t; }" : "=r"(a) : "l"(p));
    return a;
}

// ---------------- scratch (device globals; no allocs allowed) ----------------
__device__ float g_h[MM*DD];
__device__ float g_x1[MM*DD];         // fp32 gemm out for LN residual
__device__ float g_ks[BHH*NCC*DHH];
__device__ int   g_len[BB];

// chunk states as fp16 hi/lo split (exact to ~2^-22)
__device__ __align__(16) __half g_Sh[(size_t)BHH*NCC*DHH*DHH];
__device__ __align__(16) __half g_Sl[(size_t)BHH*NCC*DHH*DHH];

// fp16 activations
__device__ __align__(16) __half g_hf[MM*DD];             // residual stream as GEMM-A
__device__ __align__(16) __half g_qh[MM*DD];             // phi(q)
__device__ __align__(16) __half g_kh[MM*DD];             // masked phi(k)
__device__ __align__(16) __half g_vh[MM*DD];             // v
__device__ __align__(16) __half g_af[MM*DD];             // attention output
__device__ __align__(16) __half g_tf[(size_t)MM*FF];     // FFN hidden

// transposed weights fp16 (single-rounded): layout [N][K]
__device__ __align__(16) __half g_wq[NLL*DD*DD];
__device__ __align__(16) __half g_wk[NLL*DD*DD];
__device__ __align__(16) __half g_wv[NLL*DD*DD];
__device__ __align__(16) __half g_wo[NLL*DD*DD];
__device__ __align__(16) __half g_w1[NLL*FF*DD];
__device__ __align__(16) __half g_w2[NLL*DD*FF];

__device__ __forceinline__ float phi_f(float u) { return u > 0.f ? u + 1.f : __expf(u); }

// ---------------- lengths ----------------
__global__ void len_kernel(const int* __restrict__ x) {
    __shared__ int red[256];
    int b = blockIdx.x, tid = threadIdx.x;
    int cnt = 0;
    for (int s = tid; s < SS; s += 256) cnt += (x[b*SS + s] != 0);
    red[tid] = cnt; __syncthreads();
    for (int off = 128; off; off >>= 1) {
        if (tid < off) red[tid] += red[tid + off];
        __syncthreads();
    }
    if (tid == 0) g_len[b] = red[0];
}

// ---------------- embedding + positional (+ fp16 round) ----------------
__global__ void embed_kernel(const int* __restrict__ x,
                             const float* __restrict__ emb,
                             const float* __restrict__ pe) {
    int idx = blockIdx.x * 256 + threadIdx.x;
    if (idx >= MM * (DD/4)) return;
    int i  = idx >> 7;
    int d4 = idx & 127;
    int s  = i & (SS - 1);
    int tok = x[i];
    float4 e = ((const float4*)emb)[(size_t)tok * (DD/4) + d4];
    float4 p = ((const float4*)pe)[(size_t)s * (DD/4) + d4];
    float4 o;
    o.x = e.x + p.x; o.y = e.y + p.y; o.z = e.z + p.z; o.w = e.w + p.w;
    ((float4*)g_h)[idx] = o;
    size_t e0 = (size_t)idx * 4;
    g_hf[e0+0] = __float2half_rn(o.x);
    g_hf[e0+1] = __float2half_rn(o.y);
    g_hf[e0+2] = __float2half_rn(o.z);
    g_hf[e0+3] = __float2half_rn(o.w);
}

// ---------------- batched weight transpose + fp16 round (24 matrices) ----------
struct WtcArgs {
    const float* src[24];
    __half* oh[24];
    int K[24], N[24];
};
__global__ void wtc_all_kernel(WtcArgs p) {
    __shared__ float t[32][33];
    int m = blockIdx.z;
    int K = p.K[m], N = p.N[m];
    int n0 = blockIdx.x * 32, k0 = blockIdx.y * 32;
    if (n0 >= N || k0 >= K) return;
    const float* W = p.src[m];
    __half *oh = p.oh[m];
    int tx = threadIdx.x, ty = threadIdx.y;   // 32x8
    #pragma unroll
    for (int i = 0; i < 32; i += 8)
        t[ty + i][tx] = W[(size_t)(k0 + ty + i) * N + n0 + tx];
    __syncthreads();
    #pragma unroll
    for (int i = 0; i < 32; i += 8) {
        float v = t[tx][ty + i];
        oh[(size_t)(n0 + ty + i) * K + k0 + tx] = __float2half_rn(v);
    }
}

// ---------------- single-term fp16 GEMM via warp mma.sync (locked config) ------
struct GTArgs {
    const __half *Af;
    const __half *Bf[3];
    const float* bias[3];
    float* outf[3];
    __half* outh[3];
    int pmode[3];
    int N, K;
};

#define STAGES 4
#define TILE_BYTES 8192                    // 128 rows x 64B (swizzled)
#define STAGE_BYTES (2*TILE_BYTES)         // Af,Bf = 16384
#define GM_SMEM_BYTES (STAGES*STAGE_BYTES) // 65536

__device__ __forceinline__ uint32_t swz(int row, int c) {
    return (uint32_t)(row * 64 + ((c ^ ((row >> 1) & 3)) << 4));
}

#define MMA_F16(d, a, b) \
    asm volatile("mma.sync.aligned.m16n8k16.row.col.f32.f16.f16.f32 " \
        "{%0,%1,%2,%3}, {%4,%5,%6,%7}, {%8,%9}, {%0,%1,%2,%3};" \
        : "+f"((d)[0]), "+f"((d)[1]), "+f"((d)[2]), "+f"((d)[3]) \
        : "r"((a)[0]), "r"((a)[1]), "r"((a)[2]), "r"((a)[3]), "r"((b)[0]), "r"((b)[1]))

#define LDMX4(r, addr) \
    asm volatile("ldmatrix.sync.aligned.m8n8.x4.shared.b16 {%0,%1,%2,%3}, [%4];" \
        : "=r"((r)[0]), "=r"((r)[1]), "=r"((r)[2]), "=r"((r)[3]) : "r"(addr))

#define LDMX4T(r, addr) \
    asm volatile("ldmatrix.sync.aligned.m8n8.x4.trans.shared.b16 {%0,%1,%2,%3}, [%4];" \
        : "=r"((r)[0]), "=r"((r)[1]), "=r"((r)[2]), "=r"((r)[3]) : "r"(addr))

template<int RELU, int OUTH>
__global__ void __launch_bounds__(256, 2) gemm_mma(GTArgs p) {
    extern __shared__ __half sm[];
    const uint32_t sbase = smem_u32(sm);
    const int z = blockIdx.z;
    const int N = p.N, K = p.K;
    const int tid = threadIdx.x;
    const int m0 = blockIdx.y * 128, n0 = blockIdx.x * 128;

    const int rA  = tid >> 2;
    const int chk = tid & 3;
    const __half* gp[2];
    gp[0] = p.Af    + (size_t)(m0 + rA) * K + chk * 8;
    gp[1] = p.Bf[z] + (size_t)(n0 + rA) * K + chk * 8;
    const uint32_t s0 = swz(rA, chk);
    const size_t K64 = (size_t)K << 6;

    const int wid = tid >> 5, lane = tid & 31;
    const int wm = (wid & 1) * 64;
    const int wn = (wid >> 1) * 32;

    const int rowa = wm + (lane & 15);
    const uint32_t aSw = swz(rowa, (lane >> 4) & 1);
    const int rowb = wn + (lane & 7) + ((lane >> 4) << 3);
    const uint32_t bSw = (uint32_t)TILE_BYTES + swz(rowb, (lane >> 3) & 1);

    float acc[4][4][4];
    #pragma unroll
    for (int a = 0; a < 4; a++)
        #pragma unroll
        for (int b = 0; b < 4; b++)
            #pragma unroll
            for (int c = 0; c < 4; c++) acc[a][b][c] = 0.f;

    const int nt = K >> 5;

    auto load_stage = [&](int slot, int k0) {
        uint32_t sb = sbase + (uint32_t)slot * STAGE_BYTES + s0;
        #pragma unroll
        for (int op = 0; op < 2; op++)
            #pragma unroll
            for (int j = 0; j < 2; j++) {
                asm volatile("cp.async.cg.shared.global [%0], [%1], 16;"
                    :: "r"(sb + (uint32_t)(op * TILE_BYTES + j * 4096)),
                       "l"(gp[op] + (j ? K64 : 0) + k0));
            }
        asm volatile("cp.async.commit_group;" ::: "memory");
    };

    load_stage(0, 0);
    load_stage(1, 32);
    load_stage(2, 64);

    int cslot = 0, lslot = 3;
    for (int t = 0; t < nt; t++) {
        asm volatile("cp.async.wait_group 2;" ::: "memory");
        __syncthreads();
        if (t + 3 < nt) load_stage(lslot, (t + 3) * 32);
        else asm volatile("cp.async.commit_group;" ::: "memory");
        if (++lslot == STAGES) lslot = 0;

        const uint32_t stg = sbase + (uint32_t)cslot * STAGE_BYTES;
        if (++cslot == STAGES) cslot = 0;
        #pragma unroll
        for (int kh = 0; kh < 2; kh++) {
            const uint32_t kx = (uint32_t)(kh * 0x20);
            uint32_t bfr[2][4];
            #pragma unroll
            for (int ng = 0; ng < 2; ng++)
                LDMX4(bfr[ng], stg + ((bSw + (uint32_t)(ng * 1024)) ^ kx));
            uint32_t afr[4][4];
            #pragma unroll
            for (int mt = 0; mt < 4; mt++)
                LDMX4(afr[mt], stg + ((aSw + (uint32_t)(mt * 1024)) ^ kx));
            #pragma unroll
            for (int mt = 0; mt < 4; mt++)
                #pragma unroll
                for (int nn = 0; nn < 4; nn++) {
                    int ng = nn >> 1, hb = (nn & 1) * 2;
                    uint32_t b2[2] = { bfr[ng][hb], bfr[ng][hb+1] };
                    MMA_F16(acc[mt][nn], afr[mt], b2);
                }
        }
    }

    const float* bias = p.bias[z];
    const int pm = p.pmode[z];
    const int lenb = g_len[m0 >> 11];
    #pragma unroll
    for (int nn = 0; nn < 4; nn++) {
        int cn = n0 + wn + nn * 8 + (lane & 3) * 2;
        float b0v = bias[cn], b1v = bias[cn + 1];
        #pragma unroll
        for (int mt = 0; mt < 4; mt++) {
            int r0 = m0 + wm + mt * 16 + (lane >> 2);
            #pragma unroll
            for (int half_ = 0; half_ < 2; half_++) {
                int r = r0 + half_ * 8;
                float v0 = acc[mt][nn][half_*2 + 0] + b0v;
                float v1 = acc[mt][nn][half_*2 + 1] + b1v;
                if (RELU) { v0 = fmaxf(v0, 0.f); v1 = fmaxf(v1, 0.f); }
                if (pm == 1) { v0 = phi_f(v0); v1 = phi_f(v1); }
                else if (pm == 2) {
                    if ((r & (SS - 1)) < lenb) { v0 = phi_f(v0); v1 = phi_f(v1); }
                    else { v0 = 0.f; v1 = 0.f; }
                }
                if (OUTH) {
                    __half2 hp;
                    hp.x = __float2half_rn(v0);
                    hp.y = __float2half_rn(v1);
                    *(__half2*)(p.outh[z] + (size_t)r * N + cn) = hp;
                } else {
                    float2 o; o.x = v0; o.y = v1;
                    *(float2*)(p.outf[z] + (size_t)r * N + cn) = o;
                }
            }
        }
    }
}

// ---- attention tile swizzle: 64 rows x 64 halves (128B), chunk c8 in 0..7 ----
__device__ __forceinline__ uint32_t tsw(int row, int c8) {
    return (uint32_t)(row * 128 + ((c8 ^ (row & 7)) << 4));
}

// ---------------- attention pass 1 (HMMA): S_c = phiK^T V (split), ks_c --------
__global__ void __launch_bounds__(256) att_sums_kernel() {
    __shared__ __align__(16) __half sK[64*64];
    __shared__ __align__(16) __half sV[64*64];
    __shared__ float psum[4][64];
    uint32_t skb = smem_u32(sK), svb = smem_u32(sV);
    int c = blockIdx.x, bh = blockIdx.y;
    int b = bh >> 3, h = bh & 7;
    int tid = threadIdx.x;

    #pragma unroll
    for (int it = 0; it < 2; it++) {
        int idx = it * 256 + tid;
        int j = idx >> 3, c8 = idx & 7;
        size_t g = ((size_t)(b*SS + c*CC + j))*DD + h*DHH + c8*8;
        uint32_t off = tsw(j, c8);
        *(uint4*)((char*)sK + off) = *(const uint4*)&g_kh[g];
        *(uint4*)((char*)sV + off) = *(const uint4*)&g_vh[g];
    }
    __syncthreads();

    // ks partials (4 partitions of j)
    {
        int d = tid & 63, part = tid >> 6;
        int d8 = d >> 3, db = (d & 7) * 2;
        float s = 0.f;
        #pragma unroll 4
        for (int j = part*16; j < part*16 + 16; j++)
            s += __half2float(*(const __half*)((const char*)sK + tsw(j, d8) + db));
        psum[part][d] = s;
    }

    int wid = tid >> 5, lane = tid & 31;
    int mi = (wid & 3) * 16;     // d base
    int eb = (wid >> 2) * 32;    // e base

    float acc[4][4];
    #pragma unroll
    for (int t = 0; t < 4; t++)
        #pragma unroll
        for (int u = 0; u < 4; u++) acc[t][u] = 0.f;

    #pragma unroll
    for (int ks = 0; ks < 4; ks++) {
        int ar = ks*16 + (lane & 7) + ((lane >> 4) << 3);
        uint32_t afr[4];
        LDMX4T(afr, skb + tsw(ar, (mi >> 3) + ((lane >> 3) & 1)));
        #pragma unroll
        for (int t2 = 0; t2 < 2; t2++) {
            uint32_t bfr[4];
            LDMX4T(bfr, svb + tsw(ar, ((eb + t2*16) >> 3) + ((lane >> 3) & 1)));
            uint32_t b0[2] = { bfr[0], bfr[2] };
            uint32_t b1[2] = { bfr[1], bfr[3] };
            MMA_F16(acc[t2*2+0], afr, b0);
            MMA_F16(acc[t2*2+1], afr, b1);
        }
    }
    __syncthreads();

    __half* Sh = &g_Sh[((size_t)(bh*NCC + c)) * (DHH*DHH)];
    __half* Sl = &g_Sl[((size_t)(bh*NCC + c)) * (DHH*DHH)];
    int r_lo = mi + (lane >> 2), r_hi = r_lo + 8;
    #pragma unroll
    for (int t = 0; t < 4; t++) {
        int e = eb + t*8 + (lane & 3)*2;
        float v0 = acc[t][0], v1 = acc[t][1], v2 = acc[t][2], v3 = acc[t][3];
        __half h0 = __float2half_rn(v0), h1 = __float2half_rn(v1);
        __half h2 = __float2half_rn(v2), h3 = __float2half_rn(v3);
        __half l0 = __float2half_rn(v0 - __half2float(h0));
        __half l1 = __float2half_rn(v1 - __half2float(h1));
        __half l2 = __float2half_rn(v2 - __half2float(h2));
        __half l3 = __float2half_rn(v3 - __half2float(h3));
        *(__half2*)&Sh[r_lo*64 + e] = __halves2half2(h0, h1);
        *(__half2*)&Sl[r_lo*64 + e] = __halves2half2(l0, l1);
        *(__half2*)&Sh[r_hi*64 + e] = __halves2half2(h2, h3);
        *(__half2*)&Sl[r_hi*64 + e] = __halves2half2(l2, l3);
    }
    if (tid < 64) {
        float s = psum[0][tid] + psum[1][tid] + psum[2][tid] + psum[3][tid];
        g_ks[(bh*NCC + c)*DHH + tid] = s;
    }
}

// ---------------- attention pass 2: exclusive prefix over chunks (parallel) -----
__global__ void __launch_bounds__(256) att_scan_kernel() {
    int bh = blockIdx.x, part = blockIdx.y, tid = threadIdx.x;
    int e0 = part * 512 + tid * 2;
    float r0 = 0.f, r1 = 0.f;
    for (int c = 0; c < NCC; c++) {
        size_t base = ((size_t)(bh*NCC + c)) * (DHH*DHH) + e0;
        __half2 hv = *(const __half2*)&g_Sh[base];
        __half2 lv = *(const __half2*)&g_Sl[base];
        float2 hf = __half22float2(hv), lf = __half22float2(lv);
        float v0 = hf.x + lf.x, v1 = hf.y + lf.y;
        __half h0 = __float2half_rn(r0), h1 = __float2half_rn(r1);
        __half l0 = __float2half_rn(r0 - __half2float(h0));
        __half l1 = __float2half_rn(r1 - __half2float(h1));
        *(__half2*)&g_Sh[base] = __halves2half2(h0, h1);
        *(__half2*)&g_Sl[base] = __halves2half2(l0, l1);
        r0 += v0; r1 += v1;
    }
    if (part == 0 && tid < DHH) {
        float rk = 0.f;
        for (int c = 0; c < NCC; c++) {
            float* kp = &g_ks[(bh*NCC + c)*DHH + tid];
            float t = *kp; *kp = rk; rk += t;
        }
    }
}

// ---------------- attention pass 3 (HMMA) ----------------
__global__ void __launch_bounds__(256) att_out_kernel() {
    __shared__ __align__(16) __half sQ[64*64];
    __shared__ __align__(16) __half sKA[64*64];   // K, later masked A (fp16)
    __shared__ __align__(16) __half sV[64*64];
    __shared__ __align__(16) __half sSh[64*64];
    __shared__ __align__(16) __half sSl[64*64];
    __shared__ float skp[64];
    __shared__ float zrow[64];
    __shared__ float zinv[64];
    uint32_t qb = smem_u32(sQ), kb = smem_u32(sKA), vb = smem_u32(sV);
    uint32_t shb = smem_u32(sSh), slb = smem_u32(sSl);

    int c = blockIdx.x, bh = blockIdx.y;
    int b = bh >> 3, h = bh & 7;
    int tid = threadIdx.x;

    const __half* ShG = &g_Sh[((size_t)(bh*NCC + c)) * (DHH*DHH)];
    const __half* SlG = &g_Sl[((size_t)(bh*NCC + c)) * (DHH*DHH)];
    #pragma unroll
    for (int it = 0; it < 2; it++) {
        int idx = it * 256 + tid;
        int r = idx >> 3, c8 = idx & 7;
        size_t g = ((size_t)(b*SS + c*CC + r))*DD + h*DHH + c8*8;
        uint32_t off = tsw(r, c8);
        *(uint4*)((char*)sQ  + off) = *(const uint4*)&g_qh[g];
        *(uint4*)((char*)sKA + off) = *(const uint4*)&g_kh[g];
        *(uint4*)((char*)sV  + off) = *(const uint4*)&g_vh[g];
        int si = r*64 + c8*8;
        *(uint4*)((char*)sSh + off) = *(const uint4*)&ShG[si];
        *(uint4*)((char*)sSl + off) = *(const uint4*)&SlG[si];
    }
    if (tid < 64) skp[tid] = g_ks[(bh*NCC + c)*DHH + tid];
    __syncthreads();

    // z init: q . k_prev
    if (tid < 64) {
        float z = 0.f;
        #pragma unroll 8
        for (int d = 0; d < 64; d++)
            z += __half2float(*(const __half*)((const char*)sQ + tsw(tid, d >> 3) + (d & 7)*2)) * skp[d];
        zrow[tid] = z;
    }

    int wid = tid >> 5, lane = tid & 31;
    int ibase = (wid & 3) * 16;
    int nb = (wid >> 2) * 32;     // j or e base (32-wide half)

    // cache Q A-fragments for all 4 k-steps (reused by QK^T and Q@S)
    uint32_t qfr[4][4];
    #pragma unroll
    for (int ks = 0; ks < 4; ks++) {
        int row = ibase + (lane & 15);
        LDMX4(qfr[ks], qb + tsw(row, ks*2 + (lane >> 4)));
    }

    // A = Q K^T
    float pk[4][4];
    #pragma unroll
    for (int t = 0; t < 4; t++)
        #pragma unroll
        for (int u = 0; u < 4; u++) pk[t][u] = 0.f;
    #pragma unroll
    for (int ks = 0; ks < 4; ks++) {
        #pragma unroll
        for (int t2 = 0; t2 < 2; t2++) {
            int row = nb + t2*16 + (lane & 7) + ((lane >> 4) << 3);
            uint32_t bfr[4];
            LDMX4(bfr, kb + tsw(row, ks*2 + ((lane >> 3) & 1)));
            uint32_t b0[2] = { bfr[0], bfr[1] };
            uint32_t b1[2] = { bfr[2], bfr[3] };
            MMA_F16(pk[t2*2+0], qfr[ks], b0);
            MMA_F16(pk[t2*2+1], qfr[ks], b1);
        }
    }
    __syncthreads();   // all warps done reading sKA as K

    // mask, row sums, store masked A (fp16) into sKA
    int i_lo = ibase + (lane >> 2), i_hi = i_lo + 8;
    float rs_lo = 0.f, rs_hi = 0.f;
    #pragma unroll
    for (int t = 0; t < 4; t++) {
        int j = nb + t*8 + (lane & 3)*2;
        float m0 = (j   <= i_lo) ? pk[t][0] : 0.f;
        float m1 = (j+1 <= i_lo) ? pk[t][1] : 0.f;
        float m2 = (j   <= i_hi) ? pk[t][2] : 0.f;
        float m3 = (j+1 <= i_hi) ? pk[t][3] : 0.f;
        rs_lo += m0 + m1;
        rs_hi += m2 + m3;
        int c8 = j >> 3, jb = (j & 7) * 2;
        *(__half2*)((char*)sKA + tsw(i_lo, c8) + jb) =
            __halves2half2(__float2half_rn(m0), __float2half_rn(m1));
        *(__half2*)((char*)sKA + tsw(i_hi, c8) + jb) =
            __halves2half2(__float2half_rn(m2), __float2half_rn(m3));
    }
    rs_lo += __shfl_xor_sync(0xffffffffu, rs_lo, 1);
    rs_lo += __shfl_xor_sync(0xffffffffu, rs_lo, 2);
    rs_hi += __shfl_xor_sync(0xffffffffu, rs_hi, 1);
    rs_hi += __shfl_xor_sync(0xffffffffu, rs_hi, 2);
    if ((lane & 3) == 0) {
        atomicAdd(&zrow[i_lo], rs_lo);
        atomicAdd(&zrow[i_hi], rs_hi);
    }
    __syncthreads();   // sKA(=A) + zrow complete
    if (tid < 64) zinv[tid] = 1.f / (zrow[tid] + 1e-6f);

    // out = Q@Sh + Q@Sl + A@V
    float ov[4][4];
    #pragma unroll
    for (int t = 0; t < 4; t++)
        #pragma unroll
        for (int u = 0; u < 4; u++) ov[t][u] = 0.f;
    #pragma unroll
    for (int ks = 0; ks < 4; ks++) {
        int row = ks*16 + (lane & 7) + ((lane >> 4) << 3);
        #pragma unroll
        for (int t2 = 0; t2 < 2; t2++) {
            uint32_t bfr[4];
            LDMX4T(bfr, shb + tsw(row, ((nb + t2*16) >> 3) + ((lane >> 3) & 1)));
            uint32_t b0[2] = { bfr[0], bfr[2] };
            uint32_t b1[2] = { bfr[1], bfr[3] };
            MMA_F16(ov[t2*2+0], qfr[ks], b0);
            MMA_F16(ov[t2*2+1], qfr[ks], b1);
        }
    }
    #pragma unroll
    for (int ks = 0; ks < 4; ks++) {
        int row = ks*16 + (lane & 7) + ((lane >> 4) << 3);
        #pragma unroll
        for (int t2 = 0; t2 < 2; t2++) {
            uint32_t bfr[4];
            LDMX4T(bfr, slb + tsw(row, ((nb + t2*16) >> 3) + ((lane >> 3) & 1)));
            uint32_t b0[2] = { bfr[0], bfr[2] };
            uint32_t b1[2] = { bfr[1], bfr[3] };
            MMA_F16(ov[t2*2+0], qfr[ks], b0);
            MMA_F16(ov[t2*2+1], qfr[ks], b1);
        }
    }
    #pragma unroll
    for (int js = 0; js < 4; js++) {
        uint32_t afr[4];
        int arow = ibase + (lane & 15);
        LDMX4(afr, kb + tsw(arow, js*2 + (lane >> 4)));
        int row = js*16 + (lane & 7) + ((lane >> 4) << 3);
        #pragma unroll
        for (int t2 = 0; t2 < 2; t2++) {
            uint32_t bfr[4];
            LDMX4T(bfr, vb + tsw(row, ((nb + t2*16) >> 3) + ((lane >> 3) & 1)));
            uint32_t b0[2] = { bfr[0], bfr[2] };
            uint32_t b1[2] = { bfr[1], bfr[3] };
            MMA_F16(ov[t2*2+0], afr, b0);
            MMA_F16(ov[t2*2+1], afr, b1);
        }
    }
    __syncthreads();   // zinv visible

    float zl = zinv[i_lo], zh = zinv[i_hi];
    size_t rg_lo = ((size_t)(b*SS + c*CC + i_lo))*DD + h*DHH;
    size_t rg_hi = ((size_t)(b*SS + c*CC + i_hi))*DD + h*DHH;
    #pragma unroll
    for (int t = 0; t < 4; t++) {
        int e = nb + t*8 + (lane & 3)*2;
        *(__half2*)&g_af[rg_lo + e] =
            __halves2half2(__float2half_rn(ov[t][0]*zl), __float2half_rn(ov[t][1]*zl));
        *(__half2*)&g_af[rg_hi + e] =
            __halves2half2(__float2half_rn(ov[t][2]*zh), __float2half_rn(ov[t][3]*zh));
    }
}

// ---------------- LayerNorm (+ residual, + optional fp16 out) ----------------
__global__ void ln_kernel(const float* __restrict__ x, const float* __restrict__ add,
                          const float* __restrict__ gamma, const float* __restrict__ beta,
                          float* __restrict__ out, __half* __restrict__ oh) {
    __shared__ float rs[4], rq[4];
    int row = blockIdx.x, tid = threadIdx.x;
    float4 v = ((const float4*)(x + (size_t)row * DD))[tid];
    if (add) {
        float4 a = ((const float4*)(add + (size_t)row * DD))[tid];
        v.x += a.x; v.y += a.y; v.z += a.z; v.w += a.w;
    }
    float s = v.x + v.y + v.z + v.w;
    float q = v.x*v.x + v.y*v.y + v.z*v.z + v.w*v.w;
    #pragma unroll
    for (int off = 16; off; off >>= 1) {
        s += __shfl_xor_sync(0xffffffffu, s, off);
        q += __shfl_xor_sync(0xffffffffu, q, off);
    }
    if ((tid & 31) == 0) { rs[tid >> 5] = s; rq[tid >> 5] = q; }
    __syncthreads();
    s = rs[0] + rs[1] + rs[2] + rs[3];
    q = rq[0] + rq[1] + rq[2] + rq[3];
    float mu   = s * (1.f / DD);
    float var  = q * (1.f / DD) - mu * mu;
    float rstd = rsqrtf(var + 1e-5f);
    float4 g  = ((const float4*)gamma)[tid];
    float4 bt = ((const float4*)beta)[tid];
    float4 o;
    o.x = (v.x - mu) * rstd * g.x + bt.x;
    o.y = (v.y - mu) * rstd * g.y + bt.y;
    o.z = (v.z - mu) * rstd * g.z + bt.z;
    o.w = (v.w - mu) * rstd * g.w + bt.w;
    ((float4*)(out + (size_t)row * DD))[tid] = o;
    if (oh) {
        size_t e0 = (size_t)row * DD + tid * 4;
        oh[e0+0] = __float2half_rn(o.x);
        oh[e0+1] = __float2half_rn(o.y);
        oh[e0+2] = __float2half_rn(o.z);
        oh[e0+3] = __float2half_rn(o.w);
    }
}

// ---------------- launch --------------------------------------------------------
extern "C" void kernel_launch(void* const* d_in, const int* in_sizes, int n_in,
                              void* d_out, int out_size) {
    (void)in_sizes; (void)n_in; (void)out_size;
    const int*   x   = (const int*)  d_in[0];
    const float* emb = (const float*)d_in[1];
    const float* pe  = (const float*)d_in[2];
    const float* Wq  = (const float*)d_in[3];
    const float* bq  = (const float*)d_in[4];
    const float* Wk  = (const float*)d_in[5];
    const float* bk  = (const float*)d_in[6];
    const float* Wv  = (const float*)d_in[7];
    const float* bv  = (const float*)d_in[8];
    const float* Wo  = (const float*)d_in[9];
    const float* bo  = (const float*)d_in[10];
    const float* W1  = (const float*)d_in[11];
    const float* b1  = (const float*)d_in[12];
    const float* W2  = (const float*)d_in[13];
    const float* b2  = (const float*)d_in[14];
    const float* g1  = (const float*)d_in[15];
    const float* be1 = (const float*)d_in[16];
    const float* g2  = (const float*)d_in[17];
    const float* be2 = (const float*)d_in[18];
    const float* gf  = (const float*)d_in[19];
    const float* bf  = (const float*)d_in[20];

    float *h, *x1;
    cudaGetSymbolAddress((void**)&h, g_h);
    cudaGetSymbolAddress((void**)&x1, g_x1);
    __half *hf, *qh, *kh2, *vh2, *af, *tf;
    cudaGetSymbolAddress((void**)&hf, g_hf);
    cudaGetSymbolAddress((void**)&qh, g_qh);
    cudaGetSymbolAddress((void**)&kh2, g_kh);
    cudaGetSymbolAddress((void**)&vh2, g_vh);
    cudaGetSymbolAddress((void**)&af, g_af);
    cudaGetSymbolAddress((void**)&tf, g_tf);
    __half *wq, *wk, *wv, *wo2, *w1, *w2;
    cudaGetSymbolAddress((void**)&wq, g_wq);
    cudaGetSymbolAddress((void**)&wk, g_wk);
    cudaGetSymbolAddress((void**)&wv, g_wv);
    cudaGetSymbolAddress((void**)&wo2, g_wo);
    cudaGetSymbolAddress((void**)&w1, g_w1);
    cudaGetSymbolAddress((void**)&w2, g_w2);

    cudaFuncSetAttribute(gemm_mma<0,0>,
                         cudaFuncAttributeMaxDynamicSharedMemorySize, GM_SMEM_BYTES);
    cudaFuncSetAttribute(gemm_mma<0,1>,
                         cudaFuncAttributeMaxDynamicSharedMemorySize, GM_SMEM_BYTES);
    cudaFuncSetAttribute(gemm_mma<1,1>,
                         cudaFuncAttributeMaxDynamicSharedMemorySize, GM_SMEM_BYTES);

    len_kernel<<<BB, 256>>>(x);
    embed_kernel<<<(MM * (DD/4) + 255) / 256, 256>>>(x, emb, pe);

    {
        WtcArgs wa = {};
        int idx = 0;
        for (int l = 0; l < NLL; l++) {
            size_t wo = (size_t)l * DD * DD;
            size_t wf = (size_t)l * DD * FF;
            wa.src[idx] = Wq + wo; wa.oh[idx] = wq + wo; wa.K[idx] = DD; wa.N[idx] = DD; idx++;
            wa.src[idx] = Wk + wo; wa.oh[idx] = wk + wo; wa.K[idx] = DD; wa.N[idx] = DD; idx++;
            wa.src[idx] = Wv + wo; wa.oh[idx] = wv + wo; wa.K[idx] = DD; wa.N[idx] = DD; idx++;
            wa.src[idx] = Wo + wo; wa.oh[idx] = wo2 + wo; wa.K[idx] = DD; wa.N[idx] = DD; idx++;
            wa.src[idx] = W1 + wf; wa.oh[idx] = w1 + wf; wa.K[idx] = DD; wa.N[idx] = FF; idx++;
            wa.src[idx] = W2 + wf; wa.oh[idx] = w2 + wf; wa.K[idx] = FF; wa.N[idx] = DD; idx++;
        }
        wtc_all_kernel<<<dim3(FF/32, FF/32, 24), dim3(32, 8)>>>(wa);
    }

    for (int l = 0; l < NLL; l++) {
        size_t wo   = (size_t)l * DD * DD;
        size_t wf   = (size_t)l * DD * FF;
        size_t boff = (size_t)l * DD;

        GTArgs ga = {};
        ga.Af = hf; ga.N = DD; ga.K = DD;
        ga.Bf[0] = wq + wo;
        ga.Bf[1] = wk + wo;
        ga.Bf[2] = wv + wo;
        ga.bias[0] = bq + boff; ga.bias[1] = bk + boff; ga.bias[2] = bv + boff;
        ga.outh[0] = qh; ga.outh[1] = kh2; ga.outh[2] = vh2;
        ga.pmode[0] = 1; ga.pmode[1] = 2; ga.pmode[2] = 0;
        gemm_mma<0,1><<<dim3(DD/128, MM/128, 3), 256, GM_SMEM_BYTES>>>(ga);

        att_sums_kernel<<<dim3(NCC, BHH), 256>>>();
        att_scan_kernel<<<dim3(BHH, 8), 256>>>();
        att_out_kernel<<<dim3(NCC, BHH), 256>>>();

        GTArgs go = {};
        go.Af = af; go.N = DD; go.K = DD;
        go.Bf[0] = wo2 + wo;
        go.bias[0] = bo + boff; go.outf[0] = x1;
        gemm_mma<0,0><<<dim3(DD/128, MM/128, 1), 256, GM_SMEM_BYTES>>>(go);

        ln_kernel<<<MM, 128>>>(h, x1, g1 + boff, be1 + boff, h, hf);

        GTArgs g1a = {};
        g1a.Af = hf; g1a.N = FF; g1a.K = DD;
        g1a.Bf[0] = w1 + wf;
        g1a.bias[0] = b1 + (size_t)l * FF;
        g1a.outh[0] = tf;
        gemm_mma<1,1><<<dim3(FF/128, MM/128, 1), 256, GM_SMEM_BYTES>>>(g1a);

        GTArgs g2a = {};
        g2a.Af = tf; g2a.N = DD; g2a.K = FF;
        g2a.Bf[0] = w2 + wf;
        g2a.bias[0] = b2 + boff; g2a.outf[0] = x1;
        gemm_mma<0,0><<<dim3(DD/128, MM/128, 1), 256, GM_SMEM_BYTES>>>(g2a);

        ln_kernel<<<MM, 128>>>(h, x1, g2 + boff, be2 + boff, h, hf);
    }

    ln_kernel<<<MM, 128>>>(h, nullptr, gf, bf, (float*)d_out, nullptr);
}